// round 11
// baseline (speedup 1.0000x reference)
#include <cuda_runtime.h>
#include <cuda_fp16.h>
#include <mma.h>
#include <stdint.h>

using namespace nvcuda;

// ============================================================================
// CNN(6x conv3d) + LSTM(32) + FC.
// Conv: wmma fp16 single-term, BK=32 double-buffered, BM=256/128/64 by COUT
//       (all layers B-fragment reuse MF=2).  IH/FC: fp16 2-term.
// LSTM: persistent kernel, W_hh resident in smem, grid barrier between steps.
// Activations NDHWC fp16.  Weights k-major.
// ============================================================================

__device__ __forceinline__ void splitw(float v, __half& h, __half& l) {
    h = __float2half_rn(v);
    l = __float2half_rn(v - __half2float(h));
}

// ---- fp16 arena ----
#define O_A1  0LL
#define O_A2  100663296LL
#define O_A3  121634816LL
#define O_A4  155189248LL
#define O_A5  161480704LL
#define O_F   169869312LL
#define O_W1  170917888LL
#define O_W2  170923008LL
#define O_W3  170959872LL
#define O_W4  171033600LL
#define O_W5  171181056LL
#define O_W6  171475968LL
#define O_WIHH 172065792LL
#define O_WIHL 176260096LL
#define O_WFH 180454400LL
#define O_WFL 180716544LL
#define O_X   180978688LL
#define O_HS  195658752LL
#define H_TOTAL 195920896LL
__device__ __half g_hh[H_TOTAL];

// ---- fp32 arena ----
#define F_XG   0LL
#define F_WTHH 1048576LL
#define F_BG   2097152LL
#define F_H0   2099200LL
#define F_H1   2107392LL
#define F_C    2115584LL
#define F_BAR  2123776LL
#define F_TOTAL 2123780LL
__device__ float g_f[F_TOTAL];

// ---- prep kernels ----
__global__ void xprep(const float* __restrict__ x, __half* __restrict__ xo) {
    long i = ((long)blockIdx.x * blockDim.x + threadIdx.x) * 4;
    float4 v = *(const float4*)(x + i);
    __half2 a = __floats2half2_rn(v.x, v.y);
    __half2 b = __floats2half2_rn(v.z, v.w);
    uint2 p;
    p.x = *reinterpret_cast<uint32_t*>(&a);
    p.y = *reinterpret_cast<uint32_t*>(&b);
    *(uint2*)(xo + i) = p;
}
__global__ void convw_all(const float* s1, const float* s2, const float* s3,
                          const float* s4, const float* s5, const float* s6,
                          __half* d1, __half* d2, __half* d3,
                          __half* d4, __half* d5, __half* d6) {
    int i = blockIdx.x * blockDim.x + threadIdx.x;
    const float* src; __half* dst;
    int CIN, COUT, Kpad; float scale = 1.f;
    if (i < 3072)        { src = s1; dst = d1; CIN = 4;   COUT = 32;  Kpad = 96;   scale = 1.f / 255.f; }
    else if (i < 21504)  { src = s2; dst = d2; CIN = 32;  COUT = 32;  Kpad = 576;  i -= 3072; }
    else if (i < 58368)  { src = s3; dst = d3; CIN = 32;  COUT = 64;  Kpad = 576;  i -= 21504; }
    else if (i < 132096) { src = s4; dst = d4; CIN = 64;  COUT = 64;  Kpad = 1152; i -= 58368; }
    else if (i < 279552) { src = s5; dst = d5; CIN = 64;  COUT = 128; Kpad = 1152; i -= 132096; }
    else if (i < 574464) { src = s6; dst = d6; CIN = 128; COUT = 128; Kpad = 2304; i -= 279552; }
    else return;
    int co = i / Kpad, kk = i % Kpad;
    float v = 0.f;
    if (kk < CIN * 18) {
        int cin = kk % CIN, tap = kk / CIN;
        v = src[(co * CIN + cin) * 18 + tap] * scale;
    }
    dst[(long)kk * COUT + co] = __float2half_rn(v);
}
__global__ void ihw_prep_t(const float* __restrict__ src,
                           __half* __restrict__ dh, __half* __restrict__ dl) {
    extern __shared__ __half ts[];
    __half* TH = ts;
    __half* TL = ts + 128 * 136;
    int tid = threadIdx.x;
    int kb = blockIdx.x * 128, nbv = blockIdx.y * 128;
    {
        int n2 = nbv + (tid >> 1);
        int g = n2 & 3, u = n2 >> 2;
        const float* srow = src + (long)(g * 512 + u) * 2048 + kb + (tid & 1) * 64;
        int klo = (tid & 1) * 64, col = tid >> 1;
#pragma unroll
        for (int q = 0; q < 16; q++) {
            float4 v = *(const float4*)(srow + q * 4);
            float vv[4] = {v.x, v.y, v.z, v.w};
#pragma unroll
            for (int e = 0; e < 4; e++) {
                __half h, l;
                splitw(vv[e], h, l);
                TH[(klo + q * 4 + e) * 136 + col] = h;
                TL[(klo + q * 4 + e) * 136 + col] = l;
            }
        }
    }
    __syncthreads();
    {
        int kl = tid >> 1, nh = (tid & 1) * 64;
        int cl = kl >> 4, sp = kl & 15;
        int k2 = sp * 128 + (kb >> 4) + cl;
        long base = (long)k2 * 2048 + nbv + nh;
#pragma unroll
        for (int q = 0; q < 8; q++) {
            *(uint4*)(dh + base + q * 8) = *(const uint4*)(TH + kl * 136 + nh + q * 8);
            *(uint4*)(dl + base + q * 8) = *(const uint4*)(TL + kl * 136 + nh + q * 8);
        }
    }
}
__global__ void wf_prep(const float* __restrict__ src, __half* __restrict__ dh,
                        __half* __restrict__ dl) {
    int i = blockIdx.x * blockDim.x + threadIdx.x;
    if (i >= 512 * 512) return;
    int n = i >> 9, k = i & 511;
    __half h, l;
    splitw(src[i], h, l);
    long o = (long)k * 512 + n;
    dh[o] = h;
    dl[o] = l;
}
__global__ void perm_hh(const float* __restrict__ src, float* __restrict__ dst) {
    int i = blockIdx.x * blockDim.x + threadIdx.x;
    if (i < 2048 * 512) {
        int r = i >> 9, k = i & 511;
        int g = r >> 9, u = r & 511;
        dst[k * 2048 + (u << 2) + g] = src[i];
    }
}
__global__ void bias_sum(const float* __restrict__ bi, const float* __restrict__ bh2,
                         float* __restrict__ dst) {
    int i = blockIdx.x * blockDim.x + threadIdx.x;
    if (i < 2048) {
        int g = i >> 9, u = i & 511;
        dst[(u << 2) + g] = bi[i] + bh2[i];
    }
}

// ============================================================================
// wmma implicit-GEMM conv, fp16 single-term, BK=32, double-buffered smem.
// BM = 256 (COUT=32) / 128 (COUT=64) / 64 (COUT=128); MF=2 everywhere.
// ============================================================================
template <int CIN, int COUT, int DIN, int HIN, int WIN, int S>
__global__ __launch_bounds__(256) void conv_wm7(
    const __half* __restrict__ ain, const __half* __restrict__ wgt,
    const float* __restrict__ bias, __half* __restrict__ aout) {
    constexpr int DOUT = DIN - 1;
    constexpr int HOUT = (S == 1) ? HIN : HIN / 2;
    constexpr int WOUT = (S == 1) ? WIN : WIN / 2;
    constexpr int Kpad = (CIN == 4) ? 96 : CIN * 18;
    constexpr int NC = Kpad / 32;
    constexpr int BM = (COUT >= 128) ? 64 : ((COUT >= 64) ? 128 : 256);
    constexpr int TPR = 256 / BM;               // 4, 2, 1 threads per A row
    constexpr int HS = 32 / TPR;                // 8, 16, 32 k per thread
    constexpr int NV = HS / 8;                  // uint4 A-vectors per thread
    constexpr int WN = (COUT >= 128) ? 4 : ((COUT >= 64) ? 2 : 1);
    constexpr int WM = 8 / WN, MF = BM / (WM * 16);   // MF == 2 in all cases
    constexpr int LDA = 40, LDB = COUT + 8, LDC = COUT + 4;
    constexpr int ASZ = BM * LDA, BSZ = 32 * LDB;
    constexpr int SST = ASZ + BSZ;
    constexpr int L2C = (CIN == 32) ? 5 : ((CIN == 64) ? 6 : 7);
    constexpr int LOADSZ = 2 * SST * 2;
    constexpr int CSZ = BM * LDC * 4;
    constexpr int SMSZ = (LOADSZ > CSZ) ? LOADSZ : CSZ;

    __shared__ __align__(16) char sm[SMSZ];
    __half* smb = (__half*)sm;
    float* Cs = (float*)sm;

    int tid = threadIdx.x, wid = tid >> 5;
    int m0 = blockIdx.x * BM;
    int r = tid / TPR;
    int h = (tid % TPR) * HS;
    int m = m0 + r;
    int ow = m % WOUT; int t1 = m / WOUT;
    int oh = t1 % HOUT; int t2 = t1 / HOUT;
    int od = t2 % DOUT; int bb = t2 / DOUT;

    constexpr int TPK = COUT / 8;
    int kb = tid / TPK, nb = (tid % TPK) * 8;
    bool bact = kb < 32;

    auto lda_r = [&](int c, uint4* va) {
#pragma unroll
        for (int j = 0; j < NV; j++) va[j] = make_uint4(0u, 0u, 0u, 0u);
        if constexpr (CIN == 4) {
            int kk0 = c * 32 + h;                 // HS taps-of-4: NV*2 taps
            uint2 tv[NV * 2];
#pragma unroll
            for (int j = 0; j < NV * 2; j++) {
                tv[j] = make_uint2(0u, 0u);
                int tap = (kk0 >> 2) + j;
                if (tap < 18) {
                    int kd = (tap >= 9) ? 1 : 0; int rr = tap - 9 * kd;
                    int kh = rr / 3, kw = rr - 3 * kh;
                    int ih = oh - 1 + kh, iw = ow - 1 + kw;
                    if ((unsigned)ih < (unsigned)HIN && (unsigned)iw < (unsigned)WIN) {
                        long g = ((((long)bb * DIN + od + kd) * HIN + ih) * WIN + iw) * 4;
                        tv[j] = *(const uint2*)(ain + g);
                    }
                }
            }
#pragma unroll
            for (int j = 0; j < NV; j++)
                va[j] = make_uint4(tv[2 * j].x, tv[2 * j].y, tv[2 * j + 1].x, tv[2 * j + 1].y);
        } else {
            int kk = c * 32 + h;
            int tap = kk >> L2C, cin = kk & (CIN - 1);
            int kd = (tap >= 9) ? 1 : 0; int rr = tap - 9 * kd;
            int kh = rr / 3, kw = rr - 3 * kh;
            int ih = oh * S - 1 + kh, iw = ow * S - 1 + kw;
            if ((unsigned)ih < (unsigned)HIN && (unsigned)iw < (unsigned)WIN) {
                long g = ((((long)bb * DIN + od + kd) * HIN + ih) * WIN + iw) * CIN + cin;
#pragma unroll
                for (int j = 0; j < NV; j++)
                    va[j] = *(const uint4*)(ain + g + 8 * j);
            }
        }
    };
    auto ldb_r = [&](int c, uint4* wv) {
        if constexpr (COUT == 128) {
            wv[0] = *(const uint4*)(wgt + (long)(c * 32 + kb) * COUT + nb);
            wv[1] = *(const uint4*)(wgt + (long)(c * 32 + kb + 16) * COUT + nb);
        } else {
            if (bact) wv[0] = *(const uint4*)(wgt + (long)(c * 32 + kb) * COUT + nb);
        }
    };
    auto store_st = [&](int st, const uint4* va, const uint4* wv) {
        __half* As = smb + st * SST;
        __half* Bs = As + ASZ;
#pragma unroll
        for (int j = 0; j < NV; j++)
            *(uint4*)(As + r * LDA + h + 8 * j) = va[j];
        if constexpr (COUT == 128) {
            *(uint4*)(Bs + kb * LDB + nb) = wv[0];
            *(uint4*)(Bs + (kb + 16) * LDB + nb) = wv[1];
        } else {
            if (bact) *(uint4*)(Bs + kb * LDB + nb) = wv[0];
        }
    };

    int wm = wid / WN, wn = wid % WN;
    wmma::fragment<wmma::accumulator, 16, 16, 16, float> acc[MF][2];
#pragma unroll
    for (int i = 0; i < MF; i++)
#pragma unroll
        for (int j = 0; j < 2; j++) wmma::fill_fragment(acc[i][j], 0.f);

    uint4 va[NV], wv[2], nva[NV], nwv[2];
#pragma unroll
    for (int j = 0; j < NV; j++) { va[j] = make_uint4(0,0,0,0); nva[j] = va[j]; }
    wv[0] = wv[1] = make_uint4(0,0,0,0); nwv[0] = nwv[1] = wv[0];
    lda_r(0, va); ldb_r(0, wv);
    store_st(0, va, wv);
    __syncthreads();
    for (int c = 0; c < NC; c++) {
        int st = c & 1;
        if (c + 1 < NC) { lda_r(c + 1, nva); ldb_r(c + 1, nwv); }
        const __half* As = smb + st * SST;
        const __half* Bs = As + ASZ;
#pragma unroll
        for (int ks = 0; ks < 2; ks++) {
            wmma::fragment<wmma::matrix_b, 16, 16, 16, __half, wmma::row_major> fb[2];
#pragma unroll
            for (int j = 0; j < 2; j++)
                wmma::load_matrix_sync(fb[j], Bs + (ks * 16) * LDB + wn * 32 + j * 16, LDB);
#pragma unroll
            for (int i = 0; i < MF; i++) {
                wmma::fragment<wmma::matrix_a, 16, 16, 16, __half, wmma::row_major> fa;
                wmma::load_matrix_sync(fa, As + ((wm * MF + i) * 16) * LDA + ks * 16, LDA);
#pragma unroll
                for (int j = 0; j < 2; j++)
                    wmma::mma_sync(acc[i][j], fa, fb[j], acc[i][j]);
            }
        }
        if (c + 1 < NC) {
            store_st(st ^ 1, nva, nwv);
            __syncthreads();
        }
    }
    __syncthreads();
#pragma unroll
    for (int i = 0; i < MF; i++)
#pragma unroll
        for (int j = 0; j < 2; j++)
            wmma::store_matrix_sync(Cs + ((wm * MF + i) * 16) * LDC + wn * 32 + j * 16,
                                    acc[i][j], LDC, wmma::mem_row_major);
    __syncthreads();
    {
        int r2 = tid / TPR, ch0 = (tid % TPR) * (COUT / TPR);
        long base = (long)(m0 + r2) * COUT + ch0;
#pragma unroll
        for (int c = 0; c < COUT / TPR; c += 4) {
            float v0 = fmaxf(Cs[r2 * LDC + ch0 + c]     + bias[ch0 + c], 0.f);
            float v1 = fmaxf(Cs[r2 * LDC + ch0 + c + 1] + bias[ch0 + c + 1], 0.f);
            float v2 = fmaxf(Cs[r2 * LDC + ch0 + c + 2] + bias[ch0 + c + 2], 0.f);
            float v3 = fmaxf(Cs[r2 * LDC + ch0 + c + 3] + bias[ch0 + c + 3], 0.f);
            __half2 p0 = __floats2half2_rn(v0, v1);
            __half2 p1 = __floats2half2_rn(v2, v3);
            uint2 p;
            p.x = *reinterpret_cast<uint32_t*>(&p0);
            p.y = *reinterpret_cast<uint32_t*>(&p1);
            *(uint2*)(aout + base + c) = p;
        }
    }
}

// ============================================================================
// wmma GEMM fp16 2-term, fp32 out, double-buffered.  CTA: 64 x 128, BK=16.
// ============================================================================
template <int NTOT, int K, bool RELU>
__global__ __launch_bounds__(256) void mm_wm4(
    const __half* __restrict__ ain,
    const __half* __restrict__ whi, const __half* __restrict__ wlo,
    const float* __restrict__ bias, float* __restrict__ out) {
    constexpr int NC = K / 16;
    constexpr int LDA = 24, LDB = 136, LDC = 132;
    constexpr int ASZ = 64 * LDA, BSZ = 16 * LDB;
    constexpr int SST = ASZ + 2 * BSZ;
    constexpr int LOADSZ = 2 * SST * 2;
    constexpr int CSZ = 64 * LDC * 4;
    constexpr int SMSZ = (LOADSZ > CSZ) ? LOADSZ : CSZ;

    __shared__ __align__(16) char sm[SMSZ];
    __half* smb = (__half*)sm;
    float* Cs = (float*)sm;

    int tid = threadIdx.x, wid = tid >> 5;
    int m0 = blockIdx.x * 64, n0 = blockIdx.y * 128;
    int r = tid >> 2, h = (tid & 3) * 4;
    long mrow = m0 + r;
    int kb = tid >> 4, nb = (tid & 15) * 8;

    auto lda_r = [&](int c, uint2& va) {
        va = *(const uint2*)(ain + mrow * K + c * 16 + h);
    };
    auto ldb_r = [&](int c, uint4& wh, uint4& wl) {
        long g = (long)(c * 16 + kb) * NTOT + n0 + nb;
        wh = *(const uint4*)(whi + g);
        wl = *(const uint4*)(wlo + g);
    };
    auto store_st = [&](int st, const uint2& va, const uint4& wh, const uint4& wl) {
        __half* As = smb + st * SST;
        __half* BsH = As + ASZ;
        __half* BsL = BsH + BSZ;
        *(uint2*)(As + r * LDA + h) = va;
        *(uint4*)(BsH + kb * LDB + nb) = wh;
        *(uint4*)(BsL + kb * LDB + nb) = wl;
    };

    int wm = wid >> 2, wn = wid & 3;
    wmma::fragment<wmma::accumulator, 16, 16, 16, float> acc[2][2];
#pragma unroll
    for (int i = 0; i < 2; i++)
#pragma unroll
        for (int j = 0; j < 2; j++) wmma::fill_fragment(acc[i][j], 0.f);

    uint2 va, nva = make_uint2(0, 0);
    uint4 wh, wl, nwh = make_uint4(0, 0, 0, 0), nwl = nwh;
    lda_r(0, va); ldb_r(0, wh, wl);
    store_st(0, va, wh, wl);
    __syncthreads();
    for (int c = 0; c < NC; c++) {
        int st = c & 1;
        if (c + 1 < NC) { lda_r(c + 1, nva); ldb_r(c + 1, nwh, nwl); }
        const __half* As = smb + st * SST;
        const __half* BsH = As + ASZ;
        const __half* BsL = BsH + BSZ;
        wmma::fragment<wmma::matrix_b, 16, 16, 16, __half, wmma::row_major> fbh[2], fbl[2];
#pragma unroll
        for (int j = 0; j < 2; j++) {
            wmma::load_matrix_sync(fbh[j], BsH + wn * 32 + j * 16, LDB);
            wmma::load_matrix_sync(fbl[j], BsL + wn * 32 + j * 16, LDB);
        }
#pragma unroll
        for (int i = 0; i < 2; i++) {
            wmma::fragment<wmma::matrix_a, 16, 16, 16, __half, wmma::row_major> fa;
            wmma::load_matrix_sync(fa, As + ((wm * 2 + i) * 16) * LDA, LDA);
#pragma unroll
            for (int j = 0; j < 2; j++) {
                wmma::mma_sync(acc[i][j], fa, fbh[j], acc[i][j]);
                wmma::mma_sync(acc[i][j], fa, fbl[j], acc[i][j]);
            }
        }
        if (c + 1 < NC) {
            store_st(st ^ 1, nva, nwh, nwl);
            __syncthreads();
        }
    }
    __syncthreads();
#pragma unroll
    for (int i = 0; i < 2; i++)
#pragma unroll
        for (int j = 0; j < 2; j++)
            wmma::store_matrix_sync(Cs + ((wm * 2 + i) * 16) * LDC + wn * 32 + j * 16,
                                    acc[i][j], LDC, wmma::mem_row_major);
    __syncthreads();
    {
        int r2 = tid >> 2, ch0 = (tid & 3) * 32;
        long base = (long)(m0 + r2) * NTOT + n0 + ch0;
#pragma unroll
        for (int c = 0; c < 32; c += 4) {
            float4 v;
            v.x = Cs[r2 * LDC + ch0 + c]     + bias[n0 + ch0 + c];
            v.y = Cs[r2 * LDC + ch0 + c + 1] + bias[n0 + ch0 + c + 1];
            v.z = Cs[r2 * LDC + ch0 + c + 2] + bias[n0 + ch0 + c + 2];
            v.w = Cs[r2 * LDC + ch0 + c + 3] + bias[n0 + ch0 + c + 3];
            if (RELU) {
                v.x = fmaxf(v.x, 0.f); v.y = fmaxf(v.y, 0.f);
                v.z = fmaxf(v.z, 0.f); v.w = fmaxf(v.w, 0.f);
            }
            *(float4*)(out + base + c) = v;
        }
    }
}

// ============================================================================
// Persistent LSTM: 64 CTAs x 256 threads (K-split 2), all 32 steps.
// ============================================================================
__global__ __launch_bounds__(256) void lstm_all(
    const float* __restrict__ xg, const float* __restrict__ wthh,
    const float* __restrict__ done, float* __restrict__ hbuf0,
    float* __restrict__ hbuf1, float* __restrict__ cbuf,
    __half* __restrict__ hs, int* __restrict__ bar) {
    extern __shared__ float smf[];
    float* Ws  = smf;                 // [512][36]
    float* shh = Ws + 512 * 36;       // [16][520]
    float* red = shh + 16 * 520;      // [128][4]

    int tid = threadIdx.x;
    int n0 = blockIdx.x * 32;

#pragma unroll
    for (int i = 0; i < 16; i++) {
        int f = i * 256 + tid;
        int k = f >> 3, cc = (f & 7) * 4;
        *(float4*)&Ws[k * 36 + cc] = *(const float4*)&wthh[(long)k * 2048 + n0 + cc];
    }

    int ks = tid >> 7;
    int lt = tid & 127;
    int tx = lt & 7, ty = lt >> 3;
    int u = (n0 >> 2) + tx;
    float creg = 0.f;
    if (ks == 0) creg = cbuf[ty * 512 + u];

    for (int t = 0; t < 32; t++) {
        const float* hin = (t & 1) ? hbuf1 : hbuf0;
        float* hout = (t & 1) ? hbuf0 : hbuf1;
#pragma unroll
        for (int i = 0; i < 8; i++) {
            int idx4 = i * 256 + tid;
            int b = idx4 >> 7, q = idx4 & 127;
            float keep = 1.f - done[t * 16 + b];
            float4 v = ((const float4*)hin)[idx4];
            v.x *= keep; v.y *= keep; v.z *= keep; v.w *= keep;
            *(float4*)&shh[b * 520 + q * 4] = v;
        }
        __syncthreads();
        float a0 = 0.f, a1 = 0.f, a2 = 0.f, a3 = 0.f;
        int kbase = ks * 256;
        const float* hrow = shh + ty * 520 + kbase;
        const float* wbase = Ws + kbase * 36 + tx * 4;
#pragma unroll 8
        for (int kk = 0; kk < 256; kk++) {
            float a = hrow[kk];
            float4 w = *(const float4*)(wbase + kk * 36);
            a0 += a * w.x; a1 += a * w.y; a2 += a * w.z; a3 += a * w.w;
        }
        if (ks == 1) {
            *(float4*)&red[lt * 4] = make_float4(a0, a1, a2, a3);
        }
        __syncthreads();
        if (ks == 0) {
            float4 rr = *(const float4*)&red[lt * 4];
            float4 xv = *(const float4*)&xg[(long)(t * 16 + ty) * 2048 + n0 + tx * 4];
            float ig = a0 + rr.x + xv.x;
            float fg = a1 + rr.y + xv.y;
            float gg = a2 + rr.z + xv.z;
            float og = a3 + rr.w + xv.w;
            float keep = 1.f - done[t * 16 + ty];
            float cold = creg * keep;
            float si = 1.f / (1.f + expf(-ig));
            float sf = 1.f / (1.f + expf(-fg));
            float so = 1.f / (1.f + expf(-og));
            float cn = sf * cold + si * tanhf(gg);
            float hn = so * tanhf(cn);
            creg = cn;
            hout[ty * 512 + u] = hn;
            hs[(long)(t * 16 + ty) * 512 + u] = __float2half_rn(hn);
        }
        __threadfence();
        __syncthreads();
        if (tid == 0) {
            atomicAdd(bar, 1);
            int target = 64 * (t + 1);
            while (atomicAdd(bar, 0) < target) __nanosleep(64);
        }
        __syncthreads();
        __threadfence();
    }
    if (ks == 0) cbuf[ty * 512 + u] = creg;
}

// ---------------------------------------------------------------------------
extern "C" void kernel_launch(void* const* d_in, const int* in_sizes, int n_in,
                              void* d_out, int out_size) {
    (void)in_sizes; (void)n_in; (void)out_size;
    __half* hh = nullptr;
    float* fa = nullptr;
    cudaGetSymbolAddress((void**)&hh, g_hh);
    cudaGetSymbolAddress((void**)&fa, g_f);

    const float* x    = (const float*)d_in[0];
    const float* done = (const float*)d_in[1];
    const float* h0   = (const float*)d_in[2];
    const float* c0   = (const float*)d_in[3];
    const float* w11  = (const float*)d_in[4];
    const float* b11  = (const float*)d_in[5];
    const float* w12  = (const float*)d_in[6];
    const float* b12  = (const float*)d_in[7];
    const float* w21  = (const float*)d_in[8];
    const float* b21  = (const float*)d_in[9];
    const float* w22  = (const float*)d_in[10];
    const float* b22  = (const float*)d_in[11];
    const float* w31  = (const float*)d_in[12];
    const float* b31  = (const float*)d_in[13];
    const float* w32  = (const float*)d_in[14];
    const float* b32  = (const float*)d_in[15];
    const float* W_ih = (const float*)d_in[16];
    const float* W_hh = (const float*)d_in[17];
    const float* b_ih = (const float*)d_in[18];
    const float* b_hh = (const float*)d_in[19];
    const float* Wf   = (const float*)d_in[20];
    const float* bf   = (const float*)d_in[21];
    float* out = (float*)d_out;

    cudaFuncSetAttribute(ihw_prep_t, cudaFuncAttributeMaxDynamicSharedMemorySize, 69632);
    cudaFuncSetAttribute(lstm_all, cudaFuncAttributeMaxDynamicSharedMemorySize, 110592);

    // ---- prep ----
    xprep<<<14336, 256>>>(x, hh + O_X);
    convw_all<<<2244, 256>>>(w11, w12, w21, w22, w31, w32,
                             hh + O_W1, hh + O_W2, hh + O_W3,
                             hh + O_W4, hh + O_W5, hh + O_W6);
    ihw_prep_t<<<dim3(16, 16), 256, 69632>>>(W_ih, hh + O_WIHH, hh + O_WIHL);
    wf_prep<<<1024, 256>>>(Wf, hh + O_WFH, hh + O_WFL);
    perm_hh<<<4096, 256>>>(W_hh, fa + F_WTHH);
    bias_sum<<<8, 256>>>(b_ih, b_hh, fa + F_BG);
    cudaMemcpyAsync(fa + F_H0, h0, 8192 * sizeof(float), cudaMemcpyDeviceToDevice, 0);
    cudaMemcpyAsync(fa + F_C,  c0, 8192 * sizeof(float), cudaMemcpyDeviceToDevice, 0);
    cudaMemsetAsync(fa + F_BAR, 0, sizeof(int), 0);

    // ---- conv stack ----
    conv_wm7<4, 32, 7, 32, 32, 1><<<12288, 256>>>(hh + O_X, hh + O_W1, b11, hh + O_A1);
    conv_wm7<32, 32, 6, 32, 32, 2><<<2560, 256>>>(hh + O_A1, hh + O_W2, b12, hh + O_A2);
    conv_wm7<32, 64, 5, 16, 16, 1><<<4096, 256>>>(hh + O_A2, hh + O_W3, b21, hh + O_A3);
    conv_wm7<64, 64, 4, 16, 16, 2><<<768, 256>>>(hh + O_A3, hh + O_W4, b22, hh + O_A4);
    conv_wm7<64, 128, 3, 8, 8, 1><<<1024, 256>>>(hh + O_A4, hh + O_W5, b31, hh + O_A5);
    conv_wm7<128, 128, 2, 8, 8, 2><<<128, 256>>>(hh + O_A5, hh + O_W6, b32, hh + O_F);

    // ---- LSTM input GEMM ----
    mm_wm4<2048, 2048, false><<<dim3(8, 16), 256>>>(
        hh + O_F, hh + O_WIHH, hh + O_WIHL, fa + F_BG, fa + F_XG);

    // ---- persistent LSTM ----
    lstm_all<<<64, 256, 110592>>>(fa + F_XG, fa + F_WTHH, done,
                                  fa + F_H0, fa + F_H1, fa + F_C,
                                  hh + O_HS, (int*)(fa + F_BAR));

    // ---- final FC + relu into d_out ----
    mm_wm4<512, 512, true><<<dim3(8, 4), 256>>>(
        hh + O_HS, hh + O_WFH, hh + O_WFL, bf, out);

    // ---- hT, cT ----
    cudaMemcpyAsync(out + 262144, fa + F_H0, 8192 * sizeof(float),
                    cudaMemcpyDeviceToDevice, 0);
    cudaMemcpyAsync(out + 270336, fa + F_C, 8192 * sizeof(float),
                    cudaMemcpyDeviceToDevice, 0);
}

// round 12
// speedup vs baseline: 1.0785x; 1.0785x over previous
#include <cuda_runtime.h>
#include <cuda_fp16.h>
#include <mma.h>
#include <stdint.h>

using namespace nvcuda;

// ============================================================================
// CNN(6x conv3d) + LSTM(32) + FC.
// Conv: wmma fp16 single-term, BK=32 double-buffered (R10 proven tiling).
// IH/FC: fp16 2-term (weights 21-bit), BK=32 double-buffered.
// LSTM: persistent kernel, W_hh resident in smem, grid barrier between steps.
// Activations NDHWC fp16.  Weights k-major.
// ============================================================================

__device__ __forceinline__ void splitw(float v, __half& h, __half& l) {
    h = __float2half_rn(v);
    l = __float2half_rn(v - __half2float(h));
}

// ---- fp16 arena ----
#define O_A1  0LL
#define O_A2  100663296LL
#define O_A3  121634816LL
#define O_A4  155189248LL
#define O_A5  161480704LL
#define O_F   169869312LL
#define O_W1  170917888LL
#define O_W2  170923008LL
#define O_W3  170959872LL
#define O_W4  171033600LL
#define O_W5  171181056LL
#define O_W6  171475968LL
#define O_WIHH 172065792LL
#define O_WIHL 176260096LL
#define O_WFH 180454400LL
#define O_WFL 180716544LL
#define O_X   180978688LL
#define O_HS  195658752LL
#define H_TOTAL 195920896LL
__device__ __half g_hh[H_TOTAL];

// ---- fp32 arena ----
#define F_XG   0LL
#define F_WTHH 1048576LL
#define F_BG   2097152LL
#define F_H0   2099200LL
#define F_H1   2107392LL
#define F_C    2115584LL
#define F_BAR  2123776LL
#define F_TOTAL 2123780LL
__device__ float g_f[F_TOTAL];

// ---- prep kernels ----
__global__ void xprep(const float* __restrict__ x, __half* __restrict__ xo) {
    long i = ((long)blockIdx.x * blockDim.x + threadIdx.x) * 4;
    float4 v = *(const float4*)(x + i);
    __half2 a = __floats2half2_rn(v.x, v.y);
    __half2 b = __floats2half2_rn(v.z, v.w);
    uint2 p;
    p.x = *reinterpret_cast<uint32_t*>(&a);
    p.y = *reinterpret_cast<uint32_t*>(&b);
    *(uint2*)(xo + i) = p;
}
__global__ void convw_all(const float* s1, const float* s2, const float* s3,
                          const float* s4, const float* s5, const float* s6,
                          __half* d1, __half* d2, __half* d3,
                          __half* d4, __half* d5, __half* d6) {
    int i = blockIdx.x * blockDim.x + threadIdx.x;
    const float* src; __half* dst;
    int CIN, COUT, Kpad; float scale = 1.f;
    if (i < 3072)        { src = s1; dst = d1; CIN = 4;   COUT = 32;  Kpad = 96;   scale = 1.f / 255.f; }
    else if (i < 21504)  { src = s2; dst = d2; CIN = 32;  COUT = 32;  Kpad = 576;  i -= 3072; }
    else if (i < 58368)  { src = s3; dst = d3; CIN = 32;  COUT = 64;  Kpad = 576;  i -= 21504; }
    else if (i < 132096) { src = s4; dst = d4; CIN = 64;  COUT = 64;  Kpad = 1152; i -= 58368; }
    else if (i < 279552) { src = s5; dst = d5; CIN = 64;  COUT = 128; Kpad = 1152; i -= 132096; }
    else if (i < 574464) { src = s6; dst = d6; CIN = 128; COUT = 128; Kpad = 2304; i -= 279552; }
    else return;
    int co = i / Kpad, kk = i % Kpad;
    float v = 0.f;
    if (kk < CIN * 18) {
        int cin = kk % CIN, tap = kk / CIN;
        v = src[(co * CIN + cin) * 18 + tap] * scale;
    }
    dst[(long)kk * COUT + co] = __float2half_rn(v);
}
__global__ void ihw_prep_t(const float* __restrict__ src,
                           __half* __restrict__ dh, __half* __restrict__ dl) {
    extern __shared__ __half ts[];
    __half* TH = ts;
    __half* TL = ts + 128 * 136;
    int tid = threadIdx.x;
    int kb = blockIdx.x * 128, nbv = blockIdx.y * 128;
    {
        int n2 = nbv + (tid >> 1);
        int g = n2 & 3, u = n2 >> 2;
        const float* srow = src + (long)(g * 512 + u) * 2048 + kb + (tid & 1) * 64;
        int klo = (tid & 1) * 64, col = tid >> 1;
#pragma unroll
        for (int q = 0; q < 16; q++) {
            float4 v = *(const float4*)(srow + q * 4);
            float vv[4] = {v.x, v.y, v.z, v.w};
#pragma unroll
            for (int e = 0; e < 4; e++) {
                __half h, l;
                splitw(vv[e], h, l);
                TH[(klo + q * 4 + e) * 136 + col] = h;
                TL[(klo + q * 4 + e) * 136 + col] = l;
            }
        }
    }
    __syncthreads();
    {
        int kl = tid >> 1, nh = (tid & 1) * 64;
        int cl = kl >> 4, sp = kl & 15;
        int k2 = sp * 128 + (kb >> 4) + cl;
        long base = (long)k2 * 2048 + nbv + nh;
#pragma unroll
        for (int q = 0; q < 8; q++) {
            *(uint4*)(dh + base + q * 8) = *(const uint4*)(TH + kl * 136 + nh + q * 8);
            *(uint4*)(dl + base + q * 8) = *(const uint4*)(TL + kl * 136 + nh + q * 8);
        }
    }
}
// wf_prep + perm_hh + bias_sum merged (range dispatch).
__global__ void misc_prep(const float* __restrict__ Wf, __half* __restrict__ wfh,
                          __half* __restrict__ wfl,
                          const float* __restrict__ Whh, float* __restrict__ wthh,
                          const float* __restrict__ bi, const float* __restrict__ bh2,
                          float* __restrict__ bg) {
    int i = blockIdx.x * blockDim.x + threadIdx.x;
    if (i < 262144) {
        int n = i >> 9, k = i & 511;
        __half h, l;
        splitw(Wf[i], h, l);
        long o = (long)k * 512 + n;
        wfh[o] = h;
        wfl[o] = l;
    } else if (i < 262144 + 1048576) {
        int j = i - 262144;
        int r = j >> 9, k = j & 511;
        int g = r >> 9, u = r & 511;
        wthh[k * 2048 + (u << 2) + g] = Whh[j];
    } else if (i < 262144 + 1048576 + 2048) {
        int j = i - 262144 - 1048576;
        int g = j >> 9, u = j & 511;
        bg[(u << 2) + g] = bi[j] + bh2[j];
    }
}

// ============================================================================
// wmma implicit-GEMM conv, fp16 single-term, BK=32, double-buffered smem.
// (R10 proven tiling: BM=128 for COUT<=64, BM=64 for COUT=128.)
// ============================================================================
template <int CIN, int COUT, int DIN, int HIN, int WIN, int S>
__global__ __launch_bounds__(256) void conv_wm6(
    const __half* __restrict__ ain, const __half* __restrict__ wgt,
    const float* __restrict__ bias, __half* __restrict__ aout) {
    constexpr int DOUT = DIN - 1;
    constexpr int HOUT = (S == 1) ? HIN : HIN / 2;
    constexpr int WOUT = (S == 1) ? WIN : WIN / 2;
    constexpr int Kpad = (CIN == 4) ? 96 : CIN * 18;
    constexpr int NC = Kpad / 32;
    constexpr int BM = (COUT >= 128) ? 64 : 128;
    constexpr int TPR = 256 / BM;
    constexpr int HS = 32 / TPR;
    constexpr int WN = (COUT >= 128) ? 4 : (COUT / 32);
    constexpr int WM = 8 / WN, MF = BM / (WM * 16);
    constexpr int LDA = 40, LDB = COUT + 8, LDC = COUT + 4;
    constexpr int ASZ = BM * LDA, BSZ = 32 * LDB;
    constexpr int SST = ASZ + BSZ;
    constexpr int L2C = (CIN == 32) ? 5 : ((CIN == 64) ? 6 : 7);
    constexpr int LOADSZ = 2 * SST * 2;
    constexpr int CSZ = BM * LDC * 4;
    constexpr int SMSZ = (LOADSZ > CSZ) ? LOADSZ : CSZ;

    __shared__ __align__(16) char sm[SMSZ];
    __half* smb = (__half*)sm;
    float* Cs = (float*)sm;

    int tid = threadIdx.x, wid = tid >> 5;
    int m0 = blockIdx.x * BM;
    int r = tid / TPR;
    int h = (tid % TPR) * HS;
    int m = m0 + r;
    int ow = m % WOUT; int t1 = m / WOUT;
    int oh = t1 % HOUT; int t2 = t1 / HOUT;
    int od = t2 % DOUT; int bb = t2 / DOUT;

    constexpr int TPK = COUT / 8;
    int kb = tid / TPK, nb = (tid % TPK) * 8;
    bool bact = kb < 32;

    auto lda_r = [&](int c, uint4* va) {
        va[0] = make_uint4(0u, 0u, 0u, 0u);
        va[1] = va[0];
        if constexpr (CIN == 4) {
            int kk0 = c * 32 + h;                // TPR==2, HS==16: 4 taps
            uint2 tv[4];
#pragma unroll
            for (int j = 0; j < 4; j++) {
                tv[j] = make_uint2(0u, 0u);
                int tap = (kk0 >> 2) + j;
                if (tap < 18) {
                    int kd = (tap >= 9) ? 1 : 0; int rr = tap - 9 * kd;
                    int kh = rr / 3, kw = rr - 3 * kh;
                    int ih = oh - 1 + kh, iw = ow - 1 + kw;
                    if ((unsigned)ih < (unsigned)HIN && (unsigned)iw < (unsigned)WIN) {
                        long g = ((((long)bb * DIN + od + kd) * HIN + ih) * WIN + iw) * 4;
                        tv[j] = *(const uint2*)(ain + g);
                    }
                }
            }
            va[0] = make_uint4(tv[0].x, tv[0].y, tv[1].x, tv[1].y);
            va[1] = make_uint4(tv[2].x, tv[2].y, tv[3].x, tv[3].y);
        } else {
            int kk = c * 32 + h;
            int tap = kk >> L2C, cin = kk & (CIN - 1);
            int kd = (tap >= 9) ? 1 : 0; int rr = tap - 9 * kd;
            int kh = rr / 3, kw = rr - 3 * kh;
            int ih = oh * S - 1 + kh, iw = ow * S - 1 + kw;
            if ((unsigned)ih < (unsigned)HIN && (unsigned)iw < (unsigned)WIN) {
                long g = ((((long)bb * DIN + od + kd) * HIN + ih) * WIN + iw) * CIN + cin;
                va[0] = *(const uint4*)(ain + g);
                if constexpr (TPR == 2) va[1] = *(const uint4*)(ain + g + 8);
            }
        }
    };
    auto ldb_r = [&](int c, uint4* wv) {
        if constexpr (COUT == 128) {
            wv[0] = *(const uint4*)(wgt + (long)(c * 32 + kb) * COUT + nb);
            wv[1] = *(const uint4*)(wgt + (long)(c * 32 + kb + 16) * COUT + nb);
        } else {
            if (bact) wv[0] = *(const uint4*)(wgt + (long)(c * 32 + kb) * COUT + nb);
        }
    };
    auto store_st = [&](int st, const uint4* va, const uint4* wv) {
        __half* As = smb + st * SST;
        __half* Bs = As + ASZ;
        *(uint4*)(As + r * LDA + h) = va[0];
        if constexpr (TPR == 2) *(uint4*)(As + r * LDA + h + 8) = va[1];
        if constexpr (COUT == 128) {
            *(uint4*)(Bs + kb * LDB + nb) = wv[0];
            *(uint4*)(Bs + (kb + 16) * LDB + nb) = wv[1];
        } else {
            if (bact) *(uint4*)(Bs + kb * LDB + nb) = wv[0];
        }
    };

    int wm = wid / WN, wn = wid % WN;
    wmma::fragment<wmma::accumulator, 16, 16, 16, float> acc[MF][2];
#pragma unroll
    for (int i = 0; i < MF; i++)
#pragma unroll
        for (int j = 0; j < 2; j++) wmma::fill_fragment(acc[i][j], 0.f);

    uint4 va[2], wv[2], nva[2], nwv[2];
    va[0] = va[1] = wv[0] = wv[1] = make_uint4(0, 0, 0, 0);
    nva[0] = nva[1] = nwv[0] = nwv[1] = va[0];
    lda_r(0, va); ldb_r(0, wv);
    store_st(0, va, wv);
    __syncthreads();
    for (int c = 0; c < NC; c++) {
        int st = c & 1;
        if (c + 1 < NC) { lda_r(c + 1, nva); ldb_r(c + 1, nwv); }
        const __half* As = smb + st * SST;
        const __half* Bs = As + ASZ;
#pragma unroll
        for (int ks = 0; ks < 2; ks++) {
            wmma::fragment<wmma::matrix_b, 16, 16, 16, __half, wmma::row_major> fb[2];
#pragma unroll
            for (int j = 0; j < 2; j++)
                wmma::load_matrix_sync(fb[j], Bs + (ks * 16) * LDB + wn * 32 + j * 16, LDB);
#pragma unroll
            for (int i = 0; i < MF; i++) {
                wmma::fragment<wmma::matrix_a, 16, 16, 16, __half, wmma::row_major> fa;
                wmma::load_matrix_sync(fa, As + ((wm * MF + i) * 16) * LDA + ks * 16, LDA);
#pragma unroll
                for (int j = 0; j < 2; j++)
                    wmma::mma_sync(acc[i][j], fa, fb[j], acc[i][j]);
            }
        }
        if (c + 1 < NC) {
            store_st(st ^ 1, nva, nwv);
            __syncthreads();
        }
    }
    __syncthreads();
#pragma unroll
    for (int i = 0; i < MF; i++)
#pragma unroll
        for (int j = 0; j < 2; j++)
            wmma::store_matrix_sync(Cs + ((wm * MF + i) * 16) * LDC + wn * 32 + j * 16,
                                    acc[i][j], LDC, wmma::mem_row_major);
    __syncthreads();
    {
        int r2 = tid / TPR, ch0 = (tid % TPR) * (COUT / TPR);
        long base = (long)(m0 + r2) * COUT + ch0;
#pragma unroll
        for (int c = 0; c < COUT / TPR; c += 4) {
            float v0 = fmaxf(Cs[r2 * LDC + ch0 + c]     + bias[ch0 + c], 0.f);
            float v1 = fmaxf(Cs[r2 * LDC + ch0 + c + 1] + bias[ch0 + c + 1], 0.f);
            float v2 = fmaxf(Cs[r2 * LDC + ch0 + c + 2] + bias[ch0 + c + 2], 0.f);
            float v3 = fmaxf(Cs[r2 * LDC + ch0 + c + 3] + bias[ch0 + c + 3], 0.f);
            __half2 p0 = __floats2half2_rn(v0, v1);
            __half2 p1 = __floats2half2_rn(v2, v3);
            uint2 p;
            p.x = *reinterpret_cast<uint32_t*>(&p0);
            p.y = *reinterpret_cast<uint32_t*>(&p1);
            *(uint2*)(aout + base + c) = p;
        }
    }
}

// ============================================================================
// wmma GEMM fp16 2-term, fp32 out, BK=32 double-buffered.  CTA: 64 x 128.
// ============================================================================
template <int NTOT, int K, bool RELU>
__global__ __launch_bounds__(256) void mm_wm5(
    const __half* __restrict__ ain,
    const __half* __restrict__ whi, const __half* __restrict__ wlo,
    const float* __restrict__ bias, float* __restrict__ out) {
    constexpr int NC = K / 32;
    constexpr int LDA = 40, LDB = 136, LDC = 132;
    constexpr int ASZ = 64 * LDA, BSZ = 32 * LDB;
    constexpr int SST = ASZ + 2 * BSZ;
    constexpr int LOADSZ = 2 * SST * 2;
    constexpr int CSZ = 64 * LDC * 4;
    constexpr int SMSZ = (LOADSZ > CSZ) ? LOADSZ : CSZ;

    __shared__ __align__(16) char sm[SMSZ];
    __half* smb = (__half*)sm;
    float* Cs = (float*)sm;

    int tid = threadIdx.x, wid = tid >> 5;
    int m0 = blockIdx.x * 64, n0 = blockIdx.y * 128;
    int r = tid >> 2, h = (tid & 3) * 8;
    long mrow = m0 + r;
    int kb = tid >> 4, nb = (tid & 15) * 8;

    auto lda_r = [&](int c, uint4& va) {
        va = *(const uint4*)(ain + mrow * K + c * 32 + h);
    };
    auto ldb_r = [&](int c, uint4* w) {
        long g0 = (long)(c * 32 + kb) * NTOT + n0 + nb;
        long g1 = (long)(c * 32 + kb + 16) * NTOT + n0 + nb;
        w[0] = *(const uint4*)(whi + g0);
        w[1] = *(const uint4*)(whi + g1);
        w[2] = *(const uint4*)(wlo + g0);
        w[3] = *(const uint4*)(wlo + g1);
    };
    auto store_st = [&](int st, const uint4& va, const uint4* w) {
        __half* As = smb + st * SST;
        __half* BsH = As + ASZ;
        __half* BsL = BsH + BSZ;
        *(uint4*)(As + r * LDA + h) = va;
        *(uint4*)(BsH + kb * LDB + nb) = w[0];
        *(uint4*)(BsH + (kb + 16) * LDB + nb) = w[1];
        *(uint4*)(BsL + kb * LDB + nb) = w[2];
        *(uint4*)(BsL + (kb + 16) * LDB + nb) = w[3];
    };

    int wm = wid >> 2, wn = wid & 3;
    wmma::fragment<wmma::accumulator, 16, 16, 16, float> acc[2][2];
#pragma unroll
    for (int i = 0; i < 2; i++)
#pragma unroll
        for (int j = 0; j < 2; j++) wmma::fill_fragment(acc[i][j], 0.f);

    uint4 va, nva = make_uint4(0, 0, 0, 0);
    uint4 w[4], nw[4];
#pragma unroll
    for (int j = 0; j < 4; j++) { w[j] = make_uint4(0, 0, 0, 0); nw[j] = w[j]; }
    lda_r(0, va); ldb_r(0, w);
    store_st(0, va, w);
    __syncthreads();
    for (int c = 0; c < NC; c++) {
        int st = c & 1;
        if (c + 1 < NC) { lda_r(c + 1, nva); ldb_r(c + 1, nw); }
        const __half* As = smb + st * SST;
        const __half* BsH = As + ASZ;
        const __half* BsL = BsH + BSZ;
#pragma unroll
        for (int ks = 0; ks < 2; ks++) {
            wmma::fragment<wmma::matrix_b, 16, 16, 16, __half, wmma::row_major> fbh[2], fbl[2];
#pragma unroll
            for (int j = 0; j < 2; j++) {
                wmma::load_matrix_sync(fbh[j], BsH + (ks * 16) * LDB + wn * 32 + j * 16, LDB);
                wmma::load_matrix_sync(fbl[j], BsL + (ks * 16) * LDB + wn * 32 + j * 16, LDB);
            }
#pragma unroll
            for (int i = 0; i < 2; i++) {
                wmma::fragment<wmma::matrix_a, 16, 16, 16, __half, wmma::row_major> fa;
                wmma::load_matrix_sync(fa, As + ((wm * 2 + i) * 16) * LDA + ks * 16, LDA);
#pragma unroll
                for (int j = 0; j < 2; j++) {
                    wmma::mma_sync(acc[i][j], fa, fbh[j], acc[i][j]);
                    wmma::mma_sync(acc[i][j], fa, fbl[j], acc[i][j]);
                }
            }
        }
        if (c + 1 < NC) {
            store_st(st ^ 1, nva, nw);
            __syncthreads();
        }
    }
    __syncthreads();
#pragma unroll
    for (int i = 0; i < 2; i++)
#pragma unroll
        for (int j = 0; j < 2; j++)
            wmma::store_matrix_sync(Cs + ((wm * 2 + i) * 16) * LDC + wn * 32 + j * 16,
                                    acc[i][j], LDC, wmma::mem_row_major);
    __syncthreads();
    {
        int r2 = tid >> 2, ch0 = (tid & 3) * 32;
        long base = (long)(m0 + r2) * NTOT + n0 + ch0;
#pragma unroll
        for (int c = 0; c < 32; c += 4) {
            float4 v;
            v.x = Cs[r2 * LDC + ch0 + c]     + bias[n0 + ch0 + c];
            v.y = Cs[r2 * LDC + ch0 + c + 1] + bias[n0 + ch0 + c + 1];
            v.z = Cs[r2 * LDC + ch0 + c + 2] + bias[n0 + ch0 + c + 2];
            v.w = Cs[r2 * LDC + ch0 + c + 3] + bias[n0 + ch0 + c + 3];
            if (RELU) {
                v.x = fmaxf(v.x, 0.f); v.y = fmaxf(v.y, 0.f);
                v.z = fmaxf(v.z, 0.f); v.w = fmaxf(v.w, 0.f);
            }
            *(float4*)(out + base + c) = v;
        }
    }
}

// ============================================================================
// Persistent LSTM: 64 CTAs x 256 threads (K-split 2), all 32 steps.
// ============================================================================
__global__ __launch_bounds__(256) void lstm_all(
    const float* __restrict__ xg, const float* __restrict__ wthh,
    const float* __restrict__ done, float* __restrict__ hbuf0,
    float* __restrict__ hbuf1, float* __restrict__ cbuf,
    __half* __restrict__ hs, int* __restrict__ bar) {
    extern __shared__ float smf[];
    float* Ws  = smf;                 // [512][36]
    float* shh = Ws + 512 * 36;       // [16][520]
    float* red = shh + 16 * 520;      // [128][4]

    int tid = threadIdx.x;
    int n0 = blockIdx.x * 32;

#pragma unroll
    for (int i = 0; i < 16; i++) {
        int f = i * 256 + tid;
        int k = f >> 3, cc = (f & 7) * 4;
        *(float4*)&Ws[k * 36 + cc] = *(const float4*)&wthh[(long)k * 2048 + n0 + cc];
    }

    int ks = tid >> 7;
    int lt = tid & 127;
    int tx = lt & 7, ty = lt >> 3;
    int u = (n0 >> 2) + tx;
    float creg = 0.f;
    if (ks == 0) creg = cbuf[ty * 512 + u];

    for (int t = 0; t < 32; t++) {
        const float* hin = (t & 1) ? hbuf1 : hbuf0;
        float* hout = (t & 1) ? hbuf0 : hbuf1;
#pragma unroll
        for (int i = 0; i < 8; i++) {
            int idx4 = i * 256 + tid;
            int b = idx4 >> 7, q = idx4 & 127;
            float keep = 1.f - done[t * 16 + b];
            float4 v = ((const float4*)hin)[idx4];
            v.x *= keep; v.y *= keep; v.z *= keep; v.w *= keep;
            *(float4*)&shh[b * 520 + q * 4] = v;
        }
        __syncthreads();
        float a0 = 0.f, a1 = 0.f, a2 = 0.f, a3 = 0.f;
        int kbase = ks * 256;
        const float* hrow = shh + ty * 520 + kbase;
        const float* wbase = Ws + kbase * 36 + tx * 4;
#pragma unroll 8
        for (int kk = 0; kk < 256; kk++) {
            float a = hrow[kk];
            float4 w = *(const float4*)(wbase + kk * 36);
            a0 += a * w.x; a1 += a * w.y; a2 += a * w.z; a3 += a * w.w;
        }
        if (ks == 1) {
            *(float4*)&red[lt * 4] = make_float4(a0, a1, a2, a3);
        }
        __syncthreads();
        if (ks == 0) {
            float4 rr = *(const float4*)&red[lt * 4];
            float4 xv = *(const float4*)&xg[(long)(t * 16 + ty) * 2048 + n0 + tx * 4];
            float ig = a0 + rr.x + xv.x;
            float fg = a1 + rr.y + xv.y;
            float gg = a2 + rr.z + xv.z;
            float og = a3 + rr.w + xv.w;
            float keep = 1.f - done[t * 16 + ty];
            float cold = creg * keep;
            float si = 1.f / (1.f + expf(-ig));
            float sf = 1.f / (1.f + expf(-fg));
            float so = 1.f / (1.f + expf(-og));
            float cn = sf * cold + si * tanhf(gg);
            float hn = so * tanhf(cn);
            creg = cn;
            hout[ty * 512 + u] = hn;
            hs[(long)(t * 16 + ty) * 512 + u] = __float2half_rn(hn);
        }
        __threadfence();
        __syncthreads();
        if (tid == 0) {
            atomicAdd(bar, 1);
            int target = 64 * (t + 1);
            while (atomicAdd(bar, 0) < target) __nanosleep(64);
        }
        __syncthreads();
        __threadfence();
    }
    if (ks == 0) cbuf[ty * 512 + u] = creg;
}

// ---------------------------------------------------------------------------
extern "C" void kernel_launch(void* const* d_in, const int* in_sizes, int n_in,
                              void* d_out, int out_size) {
    (void)in_sizes; (void)n_in; (void)out_size;
    __half* hh = nullptr;
    float* fa = nullptr;
    cudaGetSymbolAddress((void**)&hh, g_hh);
    cudaGetSymbolAddress((void**)&fa, g_f);

    const float* x    = (const float*)d_in[0];
    const float* done = (const float*)d_in[1];
    const float* h0   = (const float*)d_in[2];
    const float* c0   = (const float*)d_in[3];
    const float* w11  = (const float*)d_in[4];
    const float* b11  = (const float*)d_in[5];
    const float* w12  = (const float*)d_in[6];
    const float* b12  = (const float*)d_in[7];
    const float* w21  = (const float*)d_in[8];
    const float* b21  = (const float*)d_in[9];
    const float* w22  = (const float*)d_in[10];
    const float* b22  = (const float*)d_in[11];
    const float* w31  = (const float*)d_in[12];
    const float* b31  = (const float*)d_in[13];
    const float* w32  = (const float*)d_in[14];
    const float* b32  = (const float*)d_in[15];
    const float* W_ih = (const float*)d_in[16];
    const float* W_hh = (const float*)d_in[17];
    const float* b_ih = (const float*)d_in[18];
    const float* b_hh = (const float*)d_in[19];
    const float* Wf   = (const float*)d_in[20];
    const float* bf   = (const float*)d_in[21];
    float* out = (float*)d_out;

    cudaFuncSetAttribute(ihw_prep_t, cudaFuncAttributeMaxDynamicSharedMemorySize, 69632);
    cudaFuncSetAttribute(lstm_all, cudaFuncAttributeMaxDynamicSharedMemorySize, 110592);

    // ---- prep ----
    xprep<<<14336, 256>>>(x, hh + O_X);
    convw_all<<<2244, 256>>>(w11, w12, w21, w22, w31, w32,
                             hh + O_W1, hh + O_W2, hh + O_W3,
                             hh + O_W4, hh + O_W5, hh + O_W6);
    ihw_prep_t<<<dim3(16, 16), 256, 69632>>>(W_ih, hh + O_WIHH, hh + O_WIHL);
    misc_prep<<<5128, 256>>>(Wf, hh + O_WFH, hh + O_WFL, W_hh, fa + F_WTHH,
                             b_ih, b_hh, fa + F_BG);
    cudaMemcpyAsync(fa + F_H0, h0, 8192 * sizeof(float), cudaMemcpyDeviceToDevice, 0);
    cudaMemcpyAsync(fa + F_C,  c0, 8192 * sizeof(float), cudaMemcpyDeviceToDevice, 0);
    cudaMemsetAsync(fa + F_BAR, 0, sizeof(int), 0);

    // ---- conv stack (R10 proven tiling) ----
    conv_wm6<4, 32, 7, 32, 32, 1><<<24576, 256>>>(hh + O_X, hh + O_W1, b11, hh + O_A1);
    conv_wm6<32, 32, 6, 32, 32, 2><<<5120, 256>>>(hh + O_A1, hh + O_W2, b12, hh + O_A2);
    conv_wm6<32, 64, 5, 16, 16, 1><<<4096, 256>>>(hh + O_A2, hh + O_W3, b21, hh + O_A3);
    conv_wm6<64, 64, 4, 16, 16, 2><<<768, 256>>>(hh + O_A3, hh + O_W4, b22, hh + O_A4);
    conv_wm6<64, 128, 3, 8, 8, 1><<<1024, 256>>>(hh + O_A4, hh + O_W5, b31, hh + O_A5);
    conv_wm6<128, 128, 2, 8, 8, 2><<<128, 256>>>(hh + O_A5, hh + O_W6, b32, hh + O_F);

    // ---- LSTM input GEMM (BK=32) ----
    mm_wm5<2048, 2048, false><<<dim3(8, 16), 256>>>(
        hh + O_F, hh + O_WIHH, hh + O_WIHL, fa + F_BG, fa + F_XG);

    // ---- persistent LSTM ----
    lstm_all<<<64, 256, 110592>>>(fa + F_XG, fa + F_WTHH, done,
                                  fa + F_H0, fa + F_H1, fa + F_C,
                                  hh + O_HS, (int*)(fa + F_BAR));

    // ---- final FC + relu into d_out (BK=32) ----
    mm_wm5<512, 512, true><<<dim3(8, 4), 256>>>(
        hh + O_HS, hh + O_WFH, hh + O_WFL, bf, out);

    // ---- hT, cT ----
    cudaMemcpyAsync(out + 262144, fa + F_H0, 8192 * sizeof(float),
                    cudaMemcpyDeviceToDevice, 0);
    cudaMemcpyAsync(out + 270336, fa + F_C, 8192 * sizeof(float),
                    cudaMemcpyDeviceToDevice, 0);
}

// round 13
// speedup vs baseline: 1.0953x; 1.0156x over previous
#include <cuda_runtime.h>
#include <cuda_fp16.h>
#include <mma.h>
#include <stdint.h>

using namespace nvcuda;

// ============================================================================
// CNN(6x conv3d) + LSTM(32) + FC.
// Conv: wmma fp16 single-term, BK=32 double-buffered; L6 split-K=4.
// IH/FC: fp16 2-term (weights 21-bit), BK=32 double-buffered.
// LSTM: persistent kernel, W_hh resident in smem, grid barrier between steps.
// Activations NDHWC fp16.  Weights k-major.
// ============================================================================

__device__ __forceinline__ void splitw(float v, __half& h, __half& l) {
    h = __float2half_rn(v);
    l = __float2half_rn(v - __half2float(h));
}

// ---- fp16 arena ----
#define O_A1  0LL
#define O_A2  100663296LL
#define O_A3  121634816LL
#define O_A4  155189248LL
#define O_A5  161480704LL
#define O_F   169869312LL
#define O_W1  170917888LL
#define O_W2  170923008LL
#define O_W3  170959872LL
#define O_W4  171033600LL
#define O_W5  171181056LL
#define O_W6  171475968LL
#define O_WIHH 172065792LL
#define O_WIHL 176260096LL
#define O_WFH 180454400LL
#define O_WFL 180716544LL
#define O_X   180978688LL
#define O_HS  195658752LL
#define H_TOTAL 195920896LL
__device__ __half g_hh[H_TOTAL];

// ---- fp32 arena ----
#define F_XG   0LL
#define F_WTHH 1048576LL
#define F_BG   2097152LL
#define F_H0   2099200LL
#define F_H1   2107392LL
#define F_C    2115584LL
#define F_BAR  2123776LL
#define F_SCR  2123780LL
#define F_TOTAL 6318084LL
__device__ float g_f[F_TOTAL];

// ---- prep kernels ----
// xprep (x fp32 -> fp16, 14336 blocks) + convw_all (2244 blocks) merged.
__global__ void prep_x_convw(const float* __restrict__ x, __half* __restrict__ xo,
                             const float* s1, const float* s2, const float* s3,
                             const float* s4, const float* s5, const float* s6,
                             __half* d1, __half* d2, __half* d3,
                             __half* d4, __half* d5, __half* d6) {
    if (blockIdx.x < 14336) {
        long i = ((long)blockIdx.x * blockDim.x + threadIdx.x) * 4;
        float4 v = *(const float4*)(x + i);
        __half2 a = __floats2half2_rn(v.x, v.y);
        __half2 b = __floats2half2_rn(v.z, v.w);
        uint2 p;
        p.x = *reinterpret_cast<uint32_t*>(&a);
        p.y = *reinterpret_cast<uint32_t*>(&b);
        *(uint2*)(xo + i) = p;
        return;
    }
    int i = (blockIdx.x - 14336) * blockDim.x + threadIdx.x;
    const float* src; __half* dst;
    int CIN, COUT, Kpad; float scale = 1.f;
    if (i < 3072)        { src = s1; dst = d1; CIN = 4;   COUT = 32;  Kpad = 96;   scale = 1.f / 255.f; }
    else if (i < 21504)  { src = s2; dst = d2; CIN = 32;  COUT = 32;  Kpad = 576;  i -= 3072; }
    else if (i < 58368)  { src = s3; dst = d3; CIN = 32;  COUT = 64;  Kpad = 576;  i -= 21504; }
    else if (i < 132096) { src = s4; dst = d4; CIN = 64;  COUT = 64;  Kpad = 1152; i -= 58368; }
    else if (i < 279552) { src = s5; dst = d5; CIN = 64;  COUT = 128; Kpad = 1152; i -= 132096; }
    else if (i < 574464) { src = s6; dst = d6; CIN = 128; COUT = 128; Kpad = 2304; i -= 279552; }
    else return;
    int co = i / Kpad, kk = i % Kpad;
    float v = 0.f;
    if (kk < CIN * 18) {
        int cin = kk % CIN, tap = kk / CIN;
        v = src[(co * CIN + cin) * 18 + tap] * scale;
    }
    dst[(long)kk * COUT + co] = __float2half_rn(v);
}
__global__ void ihw_prep_t(const float* __restrict__ src,
                           __half* __restrict__ dh, __half* __restrict__ dl) {
    extern __shared__ __half ts[];
    __half* TH = ts;
    __half* TL = ts + 128 * 136;
    int tid = threadIdx.x;
    int kb = blockIdx.x * 128, nbv = blockIdx.y * 128;
    {
        int n2 = nbv + (tid >> 1);
        int g = n2 & 3, u = n2 >> 2;
        const float* srow = src + (long)(g * 512 + u) * 2048 + kb + (tid & 1) * 64;
        int klo = (tid & 1) * 64, col = tid >> 1;
#pragma unroll
        for (int q = 0; q < 16; q++) {
            float4 v = *(const float4*)(srow + q * 4);
            float vv[4] = {v.x, v.y, v.z, v.w};
#pragma unroll
            for (int e = 0; e < 4; e++) {
                __half h, l;
                splitw(vv[e], h, l);
                TH[(klo + q * 4 + e) * 136 + col] = h;
                TL[(klo + q * 4 + e) * 136 + col] = l;
            }
        }
    }
    __syncthreads();
    {
        int kl = tid >> 1, nh = (tid & 1) * 64;
        int cl = kl >> 4, sp = kl & 15;
        int k2 = sp * 128 + (kb >> 4) + cl;
        long base = (long)k2 * 2048 + nbv + nh;
#pragma unroll
        for (int q = 0; q < 8; q++) {
            *(uint4*)(dh + base + q * 8) = *(const uint4*)(TH + kl * 136 + nh + q * 8);
            *(uint4*)(dl + base + q * 8) = *(const uint4*)(TL + kl * 136 + nh + q * 8);
        }
    }
}
__global__ void misc_prep(const float* __restrict__ Wf, __half* __restrict__ wfh,
                          __half* __restrict__ wfl,
                          const float* __restrict__ Whh, float* __restrict__ wthh,
                          const float* __restrict__ bi, const float* __restrict__ bh2,
                          float* __restrict__ bg) {
    int i = blockIdx.x * blockDim.x + threadIdx.x;
    if (i < 262144) {
        int n = i >> 9, k = i & 511;
        __half h, l;
        splitw(Wf[i], h, l);
        long o = (long)k * 512 + n;
        wfh[o] = h;
        wfl[o] = l;
    } else if (i < 262144 + 1048576) {
        int j = i - 262144;
        int r = j >> 9, k = j & 511;
        int g = r >> 9, u = r & 511;
        wthh[k * 2048 + (u << 2) + g] = Whh[j];
    } else if (i < 262144 + 1048576 + 2048) {
        int j = i - 262144 - 1048576;
        int g = j >> 9, u = j & 511;
        bg[(u << 2) + g] = bi[j] + bh2[j];
    }
}

// ============================================================================
// wmma implicit-GEMM conv, fp16 single-term, BK=32, double-buffered smem.
// KS>1: split-K along blockIdx.y, fp32 partials to pout (no bias/relu).
// ============================================================================
template <int CIN, int COUT, int DIN, int HIN, int WIN, int S, int KS>
__global__ __launch_bounds__(256) void conv_wm6(
    const __half* __restrict__ ain, const __half* __restrict__ wgt,
    const float* __restrict__ bias, __half* __restrict__ aout,
    float* __restrict__ pout) {
    constexpr int DOUT = DIN - 1;
    constexpr int HOUT = (S == 1) ? HIN : HIN / 2;
    constexpr int WOUT = (S == 1) ? WIN : WIN / 2;
    constexpr int Kpad = (CIN == 4) ? 96 : CIN * 18;
    constexpr int NC = Kpad / 32;
    constexpr int NCP = NC / KS;
    constexpr int BM = (COUT >= 128) ? 64 : 128;
    constexpr int TPR = 256 / BM;
    constexpr int HS = 32 / TPR;
    constexpr int WN = (COUT >= 128) ? 4 : (COUT / 32);
    constexpr int WM = 8 / WN, MF = BM / (WM * 16);
    constexpr int LDA = 40, LDB = COUT + 8, LDC = COUT + 4;
    constexpr int ASZ = BM * LDA, BSZ = 32 * LDB;
    constexpr int SST = ASZ + BSZ;
    constexpr int L2C = (CIN == 32) ? 5 : ((CIN == 64) ? 6 : 7);
    constexpr int LOADSZ = 2 * SST * 2;
    constexpr int CSZ = BM * LDC * 4;
    constexpr int SMSZ = (LOADSZ > CSZ) ? LOADSZ : CSZ;

    __shared__ __align__(16) char sm[SMSZ];
    __half* smb = (__half*)sm;
    float* Cs = (float*)sm;

    int tid = threadIdx.x, wid = tid >> 5;
    int m0 = blockIdx.x * BM;
    int part = blockIdx.y;
    int c0 = part * NCP;
    int r = tid / TPR;
    int h = (tid % TPR) * HS;
    int m = m0 + r;
    int ow = m % WOUT; int t1 = m / WOUT;
    int oh = t1 % HOUT; int t2 = t1 / HOUT;
    int od = t2 % DOUT; int bb = t2 / DOUT;

    constexpr int TPK = COUT / 8;
    int kb = tid / TPK, nb = (tid % TPK) * 8;
    bool bact = kb < 32;

    auto lda_r = [&](int c, uint4* va) {
        va[0] = make_uint4(0u, 0u, 0u, 0u);
        va[1] = va[0];
        if constexpr (CIN == 4) {
            int kk0 = c * 32 + h;
            uint2 tv[4];
#pragma unroll
            for (int j = 0; j < 4; j++) {
                tv[j] = make_uint2(0u, 0u);
                int tap = (kk0 >> 2) + j;
                if (tap < 18) {
                    int kd = (tap >= 9) ? 1 : 0; int rr = tap - 9 * kd;
                    int kh = rr / 3, kw = rr - 3 * kh;
                    int ih = oh - 1 + kh, iw = ow - 1 + kw;
                    if ((unsigned)ih < (unsigned)HIN && (unsigned)iw < (unsigned)WIN) {
                        long g = ((((long)bb * DIN + od + kd) * HIN + ih) * WIN + iw) * 4;
                        tv[j] = *(const uint2*)(ain + g);
                    }
                }
            }
            va[0] = make_uint4(tv[0].x, tv[0].y, tv[1].x, tv[1].y);
            va[1] = make_uint4(tv[2].x, tv[2].y, tv[3].x, tv[3].y);
        } else {
            int kk = c * 32 + h;
            int tap = kk >> L2C, cin = kk & (CIN - 1);
            int kd = (tap >= 9) ? 1 : 0; int rr = tap - 9 * kd;
            int kh = rr / 3, kw = rr - 3 * kh;
            int ih = oh * S - 1 + kh, iw = ow * S - 1 + kw;
            if ((unsigned)ih < (unsigned)HIN && (unsigned)iw < (unsigned)WIN) {
                long g = ((((long)bb * DIN + od + kd) * HIN + ih) * WIN + iw) * CIN + cin;
                va[0] = *(const uint4*)(ain + g);
                if constexpr (TPR == 2) va[1] = *(const uint4*)(ain + g + 8);
            }
        }
    };
    auto ldb_r = [&](int c, uint4* wv) {
        if constexpr (COUT == 128) {
            wv[0] = *(const uint4*)(wgt + (long)(c * 32 + kb) * COUT + nb);
            wv[1] = *(const uint4*)(wgt + (long)(c * 32 + kb + 16) * COUT + nb);
        } else {
            if (bact) wv[0] = *(const uint4*)(wgt + (long)(c * 32 + kb) * COUT + nb);
        }
    };
    auto store_st = [&](int st, const uint4* va, const uint4* wv) {
        __half* As = smb + st * SST;
        __half* Bs = As + ASZ;
        *(uint4*)(As + r * LDA + h) = va[0];
        if constexpr (TPR == 2) *(uint4*)(As + r * LDA + h + 8) = va[1];
        if constexpr (COUT == 128) {
            *(uint4*)(Bs + kb * LDB + nb) = wv[0];
            *(uint4*)(Bs + (kb + 16) * LDB + nb) = wv[1];
        } else {
            if (bact) *(uint4*)(Bs + kb * LDB + nb) = wv[0];
        }
    };

    int wm = wid / WN, wn = wid % WN;
    wmma::fragment<wmma::accumulator, 16, 16, 16, float> acc[MF][2];
#pragma unroll
    for (int i = 0; i < MF; i++)
#pragma unroll
        for (int j = 0; j < 2; j++) wmma::fill_fragment(acc[i][j], 0.f);

    uint4 va[2], wv[2], nva[2], nwv[2];
    va[0] = va[1] = wv[0] = wv[1] = make_uint4(0, 0, 0, 0);
    nva[0] = nva[1] = nwv[0] = nwv[1] = va[0];
    lda_r(c0, va); ldb_r(c0, wv);
    store_st(0, va, wv);
    __syncthreads();
    for (int cc = 0; cc < NCP; cc++) {
        int c = c0 + cc;
        int st = cc & 1;
        if (cc + 1 < NCP) { lda_r(c + 1, nva); ldb_r(c + 1, nwv); }
        const __half* As = smb + st * SST;
        const __half* Bs = As + ASZ;
#pragma unroll
        for (int ks = 0; ks < 2; ks++) {
            if constexpr (CIN == 4) {
                if (c == 2 && ks == 1) continue;   // all-zero K padding
            }
            wmma::fragment<wmma::matrix_b, 16, 16, 16, __half, wmma::row_major> fb[2];
#pragma unroll
            for (int j = 0; j < 2; j++)
                wmma::load_matrix_sync(fb[j], Bs + (ks * 16) * LDB + wn * 32 + j * 16, LDB);
#pragma unroll
            for (int i = 0; i < MF; i++) {
                wmma::fragment<wmma::matrix_a, 16, 16, 16, __half, wmma::row_major> fa;
                wmma::load_matrix_sync(fa, As + ((wm * MF + i) * 16) * LDA + ks * 16, LDA);
#pragma unroll
                for (int j = 0; j < 2; j++)
                    wmma::mma_sync(acc[i][j], fa, fb[j], acc[i][j]);
            }
        }
        if (cc + 1 < NCP) {
            store_st(st ^ 1, nva, nwv);
            __syncthreads();
        }
    }
    __syncthreads();
#pragma unroll
    for (int i = 0; i < MF; i++)
#pragma unroll
        for (int j = 0; j < 2; j++)
            wmma::store_matrix_sync(Cs + ((wm * MF + i) * 16) * LDC + wn * 32 + j * 16,
                                    acc[i][j], LDC, wmma::mem_row_major);
    __syncthreads();
    if constexpr (KS > 1) {
        int r2 = tid / TPR, ch0 = (tid % TPR) * (COUT / TPR);
        long base = (long)part * 1048576 + (long)(m0 + r2) * COUT + ch0;
#pragma unroll
        for (int c = 0; c < COUT / TPR; c += 4)
            *(float4*)(pout + base + c) = *(const float4*)&Cs[r2 * LDC + ch0 + c];
    } else {
        int r2 = tid / TPR, ch0 = (tid % TPR) * (COUT / TPR);
        long base = (long)(m0 + r2) * COUT + ch0;
#pragma unroll
        for (int c = 0; c < COUT / TPR; c += 4) {
            float v0 = fmaxf(Cs[r2 * LDC + ch0 + c]     + bias[ch0 + c], 0.f);
            float v1 = fmaxf(Cs[r2 * LDC + ch0 + c + 1] + bias[ch0 + c + 1], 0.f);
            float v2 = fmaxf(Cs[r2 * LDC + ch0 + c + 2] + bias[ch0 + c + 2], 0.f);
            float v3 = fmaxf(Cs[r2 * LDC + ch0 + c + 3] + bias[ch0 + c + 3], 0.f);
            __half2 p0 = __floats2half2_rn(v0, v1);
            __half2 p1 = __floats2half2_rn(v2, v3);
            uint2 p;
            p.x = *reinterpret_cast<uint32_t*>(&p0);
            p.y = *reinterpret_cast<uint32_t*>(&p1);
            *(uint2*)(aout + base + c) = p;
        }
    }
}

// L6 split-K reduce: sum 4 partials + bias + relu -> fp16.
__global__ void l6_red(const float* __restrict__ scr, const float* __restrict__ bias,
                       __half* __restrict__ outp) {
    int i = (blockIdx.x * 256 + threadIdx.x) * 4;
    float4 s = *(const float4*)(scr + i);
#pragma unroll
    for (int p = 1; p < 4; p++) {
        float4 v = *(const float4*)(scr + (long)p * 1048576 + i);
        s.x += v.x; s.y += v.y; s.z += v.z; s.w += v.w;
    }
    int n = i & 127;
    float4 b = *(const float4*)(bias + n);
    s.x = fmaxf(s.x + b.x, 0.f);
    s.y = fmaxf(s.y + b.y, 0.f);
    s.z = fmaxf(s.z + b.z, 0.f);
    s.w = fmaxf(s.w + b.w, 0.f);
    __half2 p0 = __floats2half2_rn(s.x, s.y);
    __half2 p1 = __floats2half2_rn(s.z, s.w);
    uint2 p;
    p.x = *reinterpret_cast<uint32_t*>(&p0);
    p.y = *reinterpret_cast<uint32_t*>(&p1);
    *(uint2*)(outp + i) = p;
}

// ============================================================================
// wmma GEMM fp16 2-term, fp32 out, BK=32 double-buffered.  CTA: 64 x 128.
// ============================================================================
template <int NTOT, int K, bool RELU>
__global__ __launch_bounds__(256) void mm_wm5(
    const __half* __restrict__ ain,
    const __half* __restrict__ whi, const __half* __restrict__ wlo,
    const float* __restrict__ bias, float* __restrict__ out) {
    constexpr int NC = K / 32;
    constexpr int LDA = 40, LDB = 136, LDC = 132;
    constexpr int ASZ = 64 * LDA, BSZ = 32 * LDB;
    constexpr int SST = ASZ + 2 * BSZ;
    constexpr int LOADSZ = 2 * SST * 2;
    constexpr int CSZ = 64 * LDC * 4;
    constexpr int SMSZ = (LOADSZ > CSZ) ? LOADSZ : CSZ;

    __shared__ __align__(16) char sm[SMSZ];
    __half* smb = (__half*)sm;
    float* Cs = (float*)sm;

    int tid = threadIdx.x, wid = tid >> 5;
    int m0 = blockIdx.x * 64, n0 = blockIdx.y * 128;
    int r = tid >> 2, h = (tid & 3) * 8;
    long mrow = m0 + r;
    int kb = tid >> 4, nb = (tid & 15) * 8;

    auto lda_r = [&](int c, uint4& va) {
        va = *(const uint4*)(ain + mrow * K + c * 32 + h);
    };
    auto ldb_r = [&](int c, uint4* w) {
        long g0 = (long)(c * 32 + kb) * NTOT + n0 + nb;
        long g1 = (long)(c * 32 + kb + 16) * NTOT + n0 + nb;
        w[0] = *(const uint4*)(whi + g0);
        w[1] = *(const uint4*)(whi + g1);
        w[2] = *(const uint4*)(wlo + g0);
        w[3] = *(const uint4*)(wlo + g1);
    };
    auto store_st = [&](int st, const uint4& va, const uint4* w) {
        __half* As = smb + st * SST;
        __half* BsH = As + ASZ;
        __half* BsL = BsH + BSZ;
        *(uint4*)(As + r * LDA + h) = va;
        *(uint4*)(BsH + kb * LDB + nb) = w[0];
        *(uint4*)(BsH + (kb + 16) * LDB + nb) = w[1];
        *(uint4*)(BsL + kb * LDB + nb) = w[2];
        *(uint4*)(BsL + (kb + 16) * LDB + nb) = w[3];
    };

    int wm = wid >> 2, wn = wid & 3;
    wmma::fragment<wmma::accumulator, 16, 16, 16, float> acc[2][2];
#pragma unroll
    for (int i = 0; i < 2; i++)
#pragma unroll
        for (int j = 0; j < 2; j++) wmma::fill_fragment(acc[i][j], 0.f);

    uint4 va, nva = make_uint4(0, 0, 0, 0);
    uint4 w[4], nw[4];
#pragma unroll
    for (int j = 0; j < 4; j++) { w[j] = make_uint4(0, 0, 0, 0); nw[j] = w[j]; }
    lda_r(0, va); ldb_r(0, w);
    store_st(0, va, w);
    __syncthreads();
    for (int c = 0; c < NC; c++) {
        int st = c & 1;
        if (c + 1 < NC) { lda_r(c + 1, nva); ldb_r(c + 1, nw); }
        const __half* As = smb + st * SST;
        const __half* BsH = As + ASZ;
        const __half* BsL = BsH + BSZ;
#pragma unroll
        for (int ks = 0; ks < 2; ks++) {
            wmma::fragment<wmma::matrix_b, 16, 16, 16, __half, wmma::row_major> fbh[2], fbl[2];
#pragma unroll
            for (int j = 0; j < 2; j++) {
                wmma::load_matrix_sync(fbh[j], BsH + (ks * 16) * LDB + wn * 32 + j * 16, LDB);
                wmma::load_matrix_sync(fbl[j], BsL + (ks * 16) * LDB + wn * 32 + j * 16, LDB);
            }
#pragma unroll
            for (int i = 0; i < 2; i++) {
                wmma::fragment<wmma::matrix_a, 16, 16, 16, __half, wmma::row_major> fa;
                wmma::load_matrix_sync(fa, As + ((wm * 2 + i) * 16) * LDA + ks * 16, LDA);
#pragma unroll
                for (int j = 0; j < 2; j++) {
                    wmma::mma_sync(acc[i][j], fa, fbh[j], acc[i][j]);
                    wmma::mma_sync(acc[i][j], fa, fbl[j], acc[i][j]);
                }
            }
        }
        if (c + 1 < NC) {
            store_st(st ^ 1, nva, nw);
            __syncthreads();
        }
    }
    __syncthreads();
#pragma unroll
    for (int i = 0; i < 2; i++)
#pragma unroll
        for (int j = 0; j < 2; j++)
            wmma::store_matrix_sync(Cs + ((wm * 2 + i) * 16) * LDC + wn * 32 + j * 16,
                                    acc[i][j], LDC, wmma::mem_row_major);
    __syncthreads();
    {
        int r2 = tid >> 2, ch0 = (tid & 3) * 32;
        long base = (long)(m0 + r2) * NTOT + n0 + ch0;
#pragma unroll
        for (int c = 0; c < 32; c += 4) {
            float4 v;
            v.x = Cs[r2 * LDC + ch0 + c]     + bias[n0 + ch0 + c];
            v.y = Cs[r2 * LDC + ch0 + c + 1] + bias[n0 + ch0 + c + 1];
            v.z = Cs[r2 * LDC + ch0 + c + 2] + bias[n0 + ch0 + c + 2];
            v.w = Cs[r2 * LDC + ch0 + c + 3] + bias[n0 + ch0 + c + 3];
            if (RELU) {
                v.x = fmaxf(v.x, 0.f); v.y = fmaxf(v.y, 0.f);
                v.z = fmaxf(v.z, 0.f); v.w = fmaxf(v.w, 0.f);
            }
            *(float4*)(out + base + c) = v;
        }
    }
}

// ============================================================================
// Persistent LSTM: 64 CTAs x 256 threads (K-split 2), all 32 steps.
// ============================================================================
__global__ __launch_bounds__(256) void lstm_all(
    const float* __restrict__ xg, const float* __restrict__ wthh,
    const float* __restrict__ done, float* __restrict__ hbuf0,
    float* __restrict__ hbuf1, float* __restrict__ cbuf,
    __half* __restrict__ hs, int* __restrict__ bar) {
    extern __shared__ float smf[];
    float* Ws  = smf;
    float* shh = Ws + 512 * 36;
    float* red = shh + 16 * 520;

    int tid = threadIdx.x;
    int n0 = blockIdx.x * 32;

#pragma unroll
    for (int i = 0; i < 16; i++) {
        int f = i * 256 + tid;
        int k = f >> 3, cc = (f & 7) * 4;
        *(float4*)&Ws[k * 36 + cc] = *(const float4*)&wthh[(long)k * 2048 + n0 + cc];
    }

    int ks = tid >> 7;
    int lt = tid & 127;
    int tx = lt & 7, ty = lt >> 3;
    int u = (n0 >> 2) + tx;
    float creg = 0.f;
    if (ks == 0) creg = cbuf[ty * 512 + u];

    for (int t = 0; t < 32; t++) {
        const float* hin = (t & 1) ? hbuf1 : hbuf0;
        float* hout = (t & 1) ? hbuf0 : hbuf1;
#pragma unroll
        for (int i = 0; i < 8; i++) {
            int idx4 = i * 256 + tid;
            int b = idx4 >> 7, q = idx4 & 127;
            float keep = 1.f - done[t * 16 + b];
            float4 v = ((const float4*)hin)[idx4];
            v.x *= keep; v.y *= keep; v.z *= keep; v.w *= keep;
            *(float4*)&shh[b * 520 + q * 4] = v;
        }
        __syncthreads();
        float a0 = 0.f, a1 = 0.f, a2 = 0.f, a3 = 0.f;
        int kbase = ks * 256;
        const float* hrow = shh + ty * 520 + kbase;
        const float* wbase = Ws + kbase * 36 + tx * 4;
#pragma unroll 8
        for (int kk = 0; kk < 256; kk++) {
            float a = hrow[kk];
            float4 w = *(const float4*)(wbase + kk * 36);
            a0 += a * w.x; a1 += a * w.y; a2 += a * w.z; a3 += a * w.w;
        }
        if (ks == 1) {
            *(float4*)&red[lt * 4] = make_float4(a0, a1, a2, a3);
        }
        __syncthreads();
        if (ks == 0) {
            float4 rr = *(const float4*)&red[lt * 4];
            float4 xv = *(const float4*)&xg[(long)(t * 16 + ty) * 2048 + n0 + tx * 4];
            float ig = a0 + rr.x + xv.x;
            float fg = a1 + rr.y + xv.y;
            float gg = a2 + rr.z + xv.z;
            float og = a3 + rr.w + xv.w;
            float keep = 1.f - done[t * 16 + ty];
            float cold = creg * keep;
            float si = 1.f / (1.f + expf(-ig));
            float sf = 1.f / (1.f + expf(-fg));
            float so = 1.f / (1.f + expf(-og));
            float cn = sf * cold + si * tanhf(gg);
            float hn = so * tanhf(cn);
            creg = cn;
            hout[ty * 512 + u] = hn;
            hs[(long)(t * 16 + ty) * 512 + u] = __float2half_rn(hn);
        }
        __threadfence();
        __syncthreads();
        if (tid == 0) {
            atomicAdd(bar, 1);
            int target = 64 * (t + 1);
            while (atomicAdd(bar, 0) < target) __nanosleep(64);
        }
        __syncthreads();
        __threadfence();
    }
    if (ks == 0) cbuf[ty * 512 + u] = creg;
}

// ---------------------------------------------------------------------------
extern "C" void kernel_launch(void* const* d_in, const int* in_sizes, int n_in,
                              void* d_out, int out_size) {
    (void)in_sizes; (void)n_in; (void)out_size;
    __half* hh = nullptr;
    float* fa = nullptr;
    cudaGetSymbolAddress((void**)&hh, g_hh);
    cudaGetSymbolAddress((void**)&fa, g_f);

    const float* x    = (const float*)d_in[0];
    const float* done = (const float*)d_in[1];
    const float* h0   = (const float*)d_in[2];
    const float* c0   = (const float*)d_in[3];
    const float* w11  = (const float*)d_in[4];
    const float* b11  = (const float*)d_in[5];
    const float* w12  = (const float*)d_in[6];
    const float* b12  = (const float*)d_in[7];
    const float* w21  = (const float*)d_in[8];
    const float* b21  = (const float*)d_in[9];
    const float* w22  = (const float*)d_in[10];
    const float* b22  = (const float*)d_in[11];
    const float* w31  = (const float*)d_in[12];
    const float* b31  = (const float*)d_in[13];
    const float* w32  = (const float*)d_in[14];
    const float* b32  = (const float*)d_in[15];
    const float* W_ih = (const float*)d_in[16];
    const float* W_hh = (const float*)d_in[17];
    const float* b_ih = (const float*)d_in[18];
    const float* b_hh = (const float*)d_in[19];
    const float* Wf   = (const float*)d_in[20];
    const float* bf   = (const float*)d_in[21];
    float* out = (float*)d_out;

    cudaFuncSetAttribute(ihw_prep_t, cudaFuncAttributeMaxDynamicSharedMemorySize, 69632);
    cudaFuncSetAttribute(lstm_all, cudaFuncAttributeMaxDynamicSharedMemorySize, 110592);

    // ---- prep ----
    prep_x_convw<<<16580, 256>>>(x, hh + O_X, w11, w12, w21, w22, w31, w32,
                                 hh + O_W1, hh + O_W2, hh + O_W3,
                                 hh + O_W4, hh + O_W5, hh + O_W6);
    ihw_prep_t<<<dim3(16, 16), 256, 69632>>>(W_ih, hh + O_WIHH, hh + O_WIHL);
    misc_prep<<<5128, 256>>>(Wf, hh + O_WFH, hh + O_WFL, W_hh, fa + F_WTHH,
                             b_ih, b_hh, fa + F_BG);
    cudaMemcpyAsync(fa + F_H0, h0, 8192 * sizeof(float), cudaMemcpyDeviceToDevice, 0);
    cudaMemcpyAsync(fa + F_C,  c0, 8192 * sizeof(float), cudaMemcpyDeviceToDevice, 0);
    cudaMemsetAsync(fa + F_BAR, 0, sizeof(int), 0);

    // ---- conv stack ----
    conv_wm6<4, 32, 7, 32, 32, 1, 1><<<24576, 256>>>(hh + O_X, hh + O_W1, b11, hh + O_A1, nullptr);
    conv_wm6<32, 32, 6, 32, 32, 2, 1><<<5120, 256>>>(hh + O_A1, hh + O_W2, b12, hh + O_A2, nullptr);
    conv_wm6<32, 64, 5, 16, 16, 1, 1><<<4096, 256>>>(hh + O_A2, hh + O_W3, b21, hh + O_A3, nullptr);
    conv_wm6<64, 64, 4, 16, 16, 2, 1><<<768, 256>>>(hh + O_A3, hh + O_W4, b22, hh + O_A4, nullptr);
    conv_wm6<64, 128, 3, 8, 8, 1, 1><<<1024, 256>>>(hh + O_A4, hh + O_W5, b31, hh + O_A5, nullptr);
    conv_wm6<128, 128, 2, 8, 8, 2, 4><<<dim3(128, 4), 256>>>(hh + O_A5, hh + O_W6, b32, nullptr, fa + F_SCR);
    l6_red<<<1024, 256>>>(fa + F_SCR, b32, hh + O_F);

    // ---- LSTM input GEMM (BK=32) ----
    mm_wm5<2048, 2048, false><<<dim3(8, 16), 256>>>(
        hh + O_F, hh + O_WIHH, hh + O_WIHL, fa + F_BG, fa + F_XG);

    // ---- persistent LSTM ----
    lstm_all<<<64, 256, 110592>>>(fa + F_XG, fa + F_WTHH, done,
                                  fa + F_H0, fa + F_H1, fa + F_C,
                                  hh + O_HS, (int*)(fa + F_BAR));

    // ---- final FC + relu into d_out (BK=32) ----
    mm_wm5<512, 512, true><<<dim3(8, 4), 256>>>(
        hh + O_HS, hh + O_WFH, hh + O_WFL, bf, out);

    // ---- hT, cT ----
    cudaMemcpyAsync(out + 262144, fa + F_H0, 8192 * sizeof(float),
                    cudaMemcpyDeviceToDevice, 0);
    cudaMemcpyAsync(out + 270336, fa + F_C, 8192 * sizeof(float),
                    cudaMemcpyDeviceToDevice, 0);
}

// round 14
// speedup vs baseline: 1.1149x; 1.0180x over previous
#include <cuda_runtime.h>
#include <cuda_fp16.h>
#include <mma.h>
#include <stdint.h>

using namespace nvcuda;

// ============================================================================
// CNN(6x conv3d) + LSTM(32) + FC.
// Conv: wmma fp16 single-term, BK=32 double-buffered; L1-L3 fully unrolled
//       mainloop with compile-time tap geometry (ALU-bound fix); L6 split-K=4.
// IH/FC: fp16 2-term (weights 21-bit), BK=32 double-buffered.
// LSTM: persistent kernel, W_hh resident in smem, grid barrier between steps.
// Activations NDHWC fp16.  Weights k-major.
// ============================================================================

__device__ __forceinline__ void splitw(float v, __half& h, __half& l) {
    h = __float2half_rn(v);
    l = __float2half_rn(v - __half2float(h));
}

template <int I> struct IC { static constexpr int v = I; };
template <int N, int I = 0, typename F>
__device__ __forceinline__ void sfor(F&& f) {
    if constexpr (I < N) { f(IC<I>{}); sfor<N, I + 1>(f); }
}
__host__ __device__ constexpr int tkd(int t) { return t >= 9 ? 1 : 0; }
__host__ __device__ constexpr int tkh(int t) { return (t - 9 * tkd(t)) / 3; }
__host__ __device__ constexpr int tkw(int t) { return (t - 9 * tkd(t)) % 3; }

// Gather 4 consecutive taps (CIN==4), taps T0..T0+3, compile-time geometry.
template <int T0, int HIN, int WIN>
__device__ __forceinline__ void g4(uint2* tv, const __half* __restrict__ ain, long xb,
                                   bool ihok0, bool ihok2, bool iwok0, bool iwok2) {
    sfor<4>([&](auto J) {
        constexpr int TAP = T0 + decltype(J)::v;
        if constexpr (TAP < 18) {
            constexpr int kd = tkd(TAP), kh = tkh(TAP), kw = tkw(TAP);
            constexpr int DEL = (kd * HIN * WIN + (kh - 1) * WIN + (kw - 1)) * 4;
            bool p = (kh == 0 ? ihok0 : (kh == 2 ? ihok2 : true)) &&
                     (kw == 0 ? iwok0 : (kw == 2 ? iwok2 : true));
            if (p) tv[decltype(J)::v] = *(const uint2*)(ain + xb + DEL);
        }
    });
}

// ---- fp16 arena ----
#define O_A1  0LL
#define O_A2  100663296LL
#define O_A3  121634816LL
#define O_A4  155189248LL
#define O_A5  161480704LL
#define O_F   169869312LL
#define O_W1  170917888LL
#define O_W2  170923008LL
#define O_W3  170959872LL
#define O_W4  171033600LL
#define O_W5  171181056LL
#define O_W6  171475968LL
#define O_WIHH 172065792LL
#define O_WIHL 176260096LL
#define O_WFH 180454400LL
#define O_WFL 180716544LL
#define O_X   180978688LL
#define O_HS  195658752LL
#define H_TOTAL 195920896LL
__device__ __half g_hh[H_TOTAL];

// ---- fp32 arena ----
#define F_XG   0LL
#define F_WTHH 1048576LL
#define F_BG   2097152LL
#define F_H0   2099200LL
#define F_H1   2107392LL
#define F_C    2115584LL
#define F_BAR  2123776LL
#define F_SCR  2123780LL
#define F_TOTAL 6318084LL
__device__ float g_f[F_TOTAL];

// ---- prep kernels ----
__global__ void prep_x_convw(const float* __restrict__ x, __half* __restrict__ xo,
                             const float* s1, const float* s2, const float* s3,
                             const float* s4, const float* s5, const float* s6,
                             __half* d1, __half* d2, __half* d3,
                             __half* d4, __half* d5, __half* d6) {
    if (blockIdx.x < 14336) {
        long i = ((long)blockIdx.x * blockDim.x + threadIdx.x) * 4;
        float4 v = *(const float4*)(x + i);
        __half2 a = __floats2half2_rn(v.x, v.y);
        __half2 b = __floats2half2_rn(v.z, v.w);
        uint2 p;
        p.x = *reinterpret_cast<uint32_t*>(&a);
        p.y = *reinterpret_cast<uint32_t*>(&b);
        *(uint2*)(xo + i) = p;
        return;
    }
    int i = (blockIdx.x - 14336) * blockDim.x + threadIdx.x;
    const float* src; __half* dst;
    int CIN, COUT, Kpad; float scale = 1.f;
    if (i < 3072)        { src = s1; dst = d1; CIN = 4;   COUT = 32;  Kpad = 96;   scale = 1.f / 255.f; }
    else if (i < 21504)  { src = s2; dst = d2; CIN = 32;  COUT = 32;  Kpad = 576;  i -= 3072; }
    else if (i < 58368)  { src = s3; dst = d3; CIN = 32;  COUT = 64;  Kpad = 576;  i -= 21504; }
    else if (i < 132096) { src = s4; dst = d4; CIN = 64;  COUT = 64;  Kpad = 1152; i -= 58368; }
    else if (i < 279552) { src = s5; dst = d5; CIN = 64;  COUT = 128; Kpad = 1152; i -= 132096; }
    else if (i < 574464) { src = s6; dst = d6; CIN = 128; COUT = 128; Kpad = 2304; i -= 279552; }
    else return;
    int co = i / Kpad, kk = i % Kpad;
    float v = 0.f;
    if (kk < CIN * 18) {
        int cin = kk % CIN, tap = kk / CIN;
        v = src[(co * CIN + cin) * 18 + tap] * scale;
    }
    dst[(long)kk * COUT + co] = __float2half_rn(v);
}
__global__ void ihw_prep_t(const float* __restrict__ src,
                           __half* __restrict__ dh, __half* __restrict__ dl) {
    extern __shared__ __half ts[];
    __half* TH = ts;
    __half* TL = ts + 128 * 136;
    int tid = threadIdx.x;
    int kb = blockIdx.x * 128, nbv = blockIdx.y * 128;
    {
        int n2 = nbv + (tid >> 1);
        int g = n2 & 3, u = n2 >> 2;
        const float* srow = src + (long)(g * 512 + u) * 2048 + kb + (tid & 1) * 64;
        int klo = (tid & 1) * 64, col = tid >> 1;
#pragma unroll
        for (int q = 0; q < 16; q++) {
            float4 v = *(const float4*)(srow + q * 4);
            float vv[4] = {v.x, v.y, v.z, v.w};
#pragma unroll
            for (int e = 0; e < 4; e++) {
                __half h, l;
                splitw(vv[e], h, l);
                TH[(klo + q * 4 + e) * 136 + col] = h;
                TL[(klo + q * 4 + e) * 136 + col] = l;
            }
        }
    }
    __syncthreads();
    {
        int kl = tid >> 1, nh = (tid & 1) * 64;
        int cl = kl >> 4, sp = kl & 15;
        int k2 = sp * 128 + (kb >> 4) + cl;
        long base = (long)k2 * 2048 + nbv + nh;
#pragma unroll
        for (int q = 0; q < 8; q++) {
            *(uint4*)(dh + base + q * 8) = *(const uint4*)(TH + kl * 136 + nh + q * 8);
            *(uint4*)(dl + base + q * 8) = *(const uint4*)(TL + kl * 136 + nh + q * 8);
        }
    }
}
__global__ void misc_prep(const float* __restrict__ Wf, __half* __restrict__ wfh,
                          __half* __restrict__ wfl,
                          const float* __restrict__ Whh, float* __restrict__ wthh,
                          const float* __restrict__ bi, const float* __restrict__ bh2,
                          float* __restrict__ bg) {
    int i = blockIdx.x * blockDim.x + threadIdx.x;
    if (i < 262144) {
        int n = i >> 9, k = i & 511;
        __half h, l;
        splitw(Wf[i], h, l);
        long o = (long)k * 512 + n;
        wfh[o] = h;
        wfl[o] = l;
    } else if (i < 262144 + 1048576) {
        int j = i - 262144;
        int r = j >> 9, k = j & 511;
        int g = r >> 9, u = r & 511;
        wthh[k * 2048 + (u << 2) + g] = Whh[j];
    } else if (i < 262144 + 1048576 + 2048) {
        int j = i - 262144 - 1048576;
        int g = j >> 9, u = j & 511;
        bg[(u << 2) + g] = bi[j] + bh2[j];
    }
}

// ============================================================================
// wmma implicit-GEMM conv.  NC<=18 && KS==1: fully-unrolled mainloop with
// compile-time tap geometry.  Else: runtime loop (L4/L5/L6).
// ============================================================================
template <int CIN, int COUT, int DIN, int HIN, int WIN, int S, int KS>
__global__ __launch_bounds__(256) void conv_wm8(
    const __half* __restrict__ ain, const __half* __restrict__ wgt,
    const float* __restrict__ bias, __half* __restrict__ aout,
    float* __restrict__ pout) {
    constexpr int DOUT = DIN - 1;
    constexpr int HOUT = (S == 1) ? HIN : HIN / 2;
    constexpr int WOUT = (S == 1) ? WIN : WIN / 2;
    constexpr int Kpad = (CIN == 4) ? 96 : CIN * 18;
    constexpr int NC = Kpad / 32;
    constexpr int NCP = NC / KS;
    constexpr int BM = (COUT >= 128) ? 64 : 128;
    constexpr int TPR = 256 / BM;
    constexpr int HS = 32 / TPR;
    constexpr int WN = (COUT >= 128) ? 4 : (COUT / 32);
    constexpr int WM = 8 / WN, MF = BM / (WM * 16);
    constexpr int LDA = 40, LDB = COUT + 8, LDC = COUT + 4;
    constexpr int ASZ = BM * LDA, BSZ = 32 * LDB;
    constexpr int SST = ASZ + BSZ;
    constexpr int L2C = (CIN == 32) ? 5 : ((CIN == 64) ? 6 : 7);
    constexpr int LOADSZ = 2 * SST * 2;
    constexpr int CSZ = BM * LDC * 4;
    constexpr int SMSZ = (LOADSZ > CSZ) ? LOADSZ : CSZ;
    constexpr bool UNROLLED = (KS == 1) && (NC <= 18);

    __shared__ __align__(16) char sm[SMSZ];
    __half* smb = (__half*)sm;
    float* Cs = (float*)sm;

    int tid = threadIdx.x, wid = tid >> 5;
    int m0 = blockIdx.x * BM;
    int part = blockIdx.y;
    int c0 = part * NCP;
    int r = tid / TPR;
    int h = (tid % TPR) * HS;
    int m = m0 + r;
    int ow = m % WOUT; int t1 = m / WOUT;
    int oh = t1 % HOUT; int t2 = t1 / HOUT;
    int od = t2 % DOUT; int bb = t2 / DOUT;

    constexpr int TPK = COUT / 8;
    int kb = tid / TPK, nb = (tid % TPK) * 8;
    bool bact = kb < 32;

    // per-thread base + boundary predicates (for constant-delta gathers)
    long xb = ((((long)bb * DIN + od) * HIN + oh * S) * WIN + ow * S) * CIN;
    bool ihok0 = oh * S >= 1, ihok2 = oh * S + 1 < HIN;
    bool iwok0 = ow * S >= 1, iwok2 = ow * S + 1 < WIN;

    auto ldb_r = [&](int c, uint4* wv) {
        if constexpr (COUT == 128) {
            wv[0] = *(const uint4*)(wgt + (long)(c * 32 + kb) * COUT + nb);
            wv[1] = *(const uint4*)(wgt + (long)(c * 32 + kb + 16) * COUT + nb);
        } else {
            if (bact) wv[0] = *(const uint4*)(wgt + (long)(c * 32 + kb) * COUT + nb);
        }
    };
    auto store_st = [&](int st, const uint4* va, const uint4* wv) {
        __half* As = smb + st * SST;
        __half* Bs = As + ASZ;
        *(uint4*)(As + r * LDA + h) = va[0];
        if constexpr (TPR == 2) *(uint4*)(As + r * LDA + h + 8) = va[1];
        if constexpr (COUT == 128) {
            *(uint4*)(Bs + kb * LDB + nb) = wv[0];
            *(uint4*)(Bs + (kb + 16) * LDB + nb) = wv[1];
        } else {
            if (bact) *(uint4*)(Bs + kb * LDB + nb) = wv[0];
        }
    };

    int wm = wid / WN, wn = wid % WN;
    wmma::fragment<wmma::accumulator, 16, 16, 16, float> acc[MF][2];
#pragma unroll
    for (int i = 0; i < MF; i++)
#pragma unroll
        for (int j = 0; j < 2; j++) wmma::fill_fragment(acc[i][j], 0.f);

    uint4 va[2], wv[2], nva[2], nwv[2];
    va[0] = va[1] = wv[0] = wv[1] = make_uint4(0, 0, 0, 0);
    nva[0] = nva[1] = nwv[0] = nwv[1] = va[0];

    if constexpr (UNROLLED) {
        // compile-time-chunk gather
        auto gather = [&](auto C, uint4* dst) {
            constexpr int c = decltype(C)::v;
            if constexpr (CIN == 4) {
                uint2 tv[4];
                tv[0] = tv[1] = tv[2] = tv[3] = make_uint2(0u, 0u);
                if (h == 0) g4<c * 8 + 0, HIN, WIN>(tv, ain, xb, ihok0, ihok2, iwok0, iwok2);
                else        g4<c * 8 + 4, HIN, WIN>(tv, ain, xb, ihok0, ihok2, iwok0, iwok2);
                dst[0] = make_uint4(tv[0].x, tv[0].y, tv[1].x, tv[1].y);
                dst[1] = make_uint4(tv[2].x, tv[2].y, tv[3].x, tv[3].y);
            } else {
                constexpr int tap = (c * 32) / CIN;
                constexpr int kd = tkd(tap), kh = tkh(tap), kw = tkw(tap);
                constexpr int cinb = 32 * (c % (CIN / 32));
                constexpr long DEL = (long)(kd * HIN * WIN + (kh - 1) * WIN + (kw - 1)) * CIN + cinb;
                dst[0] = make_uint4(0u, 0u, 0u, 0u);
                dst[1] = dst[0];
                bool p = (kh == 0 ? ihok0 : (kh == 2 ? ihok2 : true)) &&
                         (kw == 0 ? iwok0 : (kw == 2 ? iwok2 : true));
                if (p) {
                    const __half* src = ain + xb + DEL + h;
                    dst[0] = *(const uint4*)(src);
                    if constexpr (TPR == 2) dst[1] = *(const uint4*)(src + 8);
                }
            }
        };
        gather(IC<0>{}, va); ldb_r(0, wv);
        store_st(0, va, wv);
        __syncthreads();
        sfor<NCP>([&](auto CC) {
            constexpr int cc = decltype(CC)::v;
            constexpr int st = cc & 1;
            if constexpr (cc + 1 < NCP) { gather(IC<cc + 1>{}, nva); ldb_r(cc + 1, nwv); }
            const __half* As = smb + st * SST;
            const __half* Bs = As + ASZ;
            constexpr int KSN = (CIN == 4 && cc == 2) ? 1 : 2;   // skip all-zero pad kstep
#pragma unroll
            for (int ksx = 0; ksx < KSN; ksx++) {
                wmma::fragment<wmma::matrix_b, 16, 16, 16, __half, wmma::row_major> fb[2];
#pragma unroll
                for (int j = 0; j < 2; j++)
                    wmma::load_matrix_sync(fb[j], Bs + (ksx * 16) * LDB + wn * 32 + j * 16, LDB);
#pragma unroll
                for (int i = 0; i < MF; i++) {
                    wmma::fragment<wmma::matrix_a, 16, 16, 16, __half, wmma::row_major> fa;
                    wmma::load_matrix_sync(fa, As + ((wm * MF + i) * 16) * LDA + ksx * 16, LDA);
#pragma unroll
                    for (int j = 0; j < 2; j++)
                        wmma::mma_sync(acc[i][j], fa, fb[j], acc[i][j]);
                }
            }
            if constexpr (cc + 1 < NCP) {
                store_st(st ^ 1, nva, nwv);
                __syncthreads();
            }
        });
    } else {
        // runtime loop (L4 / L5 / L6 split-K)
        auto lda_r = [&](int c, uint4* dst) {
            dst[0] = make_uint4(0u, 0u, 0u, 0u);
            dst[1] = dst[0];
            int kk = c * 32 + h;
            int tap = kk >> L2C, cin = kk & (CIN - 1);
            int kd = (tap >= 9) ? 1 : 0; int rr = tap - 9 * kd;
            int kh = rr / 3, kw = rr - 3 * kh;
            int ih = oh * S - 1 + kh, iw = ow * S - 1 + kw;
            if ((unsigned)ih < (unsigned)HIN && (unsigned)iw < (unsigned)WIN) {
                long g = ((((long)bb * DIN + od + kd) * HIN + ih) * WIN + iw) * CIN + cin;
                dst[0] = *(const uint4*)(ain + g);
                if constexpr (TPR == 2) dst[1] = *(const uint4*)(ain + g + 8);
            }
        };
        lda_r(c0, va); ldb_r(c0, wv);
        store_st(0, va, wv);
        __syncthreads();
        for (int cc = 0; cc < NCP; cc++) {
            int c = c0 + cc;
            int st = cc & 1;
            if (cc + 1 < NCP) { lda_r(c + 1, nva); ldb_r(c + 1, nwv); }
            const __half* As = smb + st * SST;
            const __half* Bs = As + ASZ;
#pragma unroll
            for (int ksx = 0; ksx < 2; ksx++) {
                wmma::fragment<wmma::matrix_b, 16, 16, 16, __half, wmma::row_major> fb[2];
#pragma unroll
                for (int j = 0; j < 2; j++)
                    wmma::load_matrix_sync(fb[j], Bs + (ksx * 16) * LDB + wn * 32 + j * 16, LDB);
#pragma unroll
                for (int i = 0; i < MF; i++) {
                    wmma::fragment<wmma::matrix_a, 16, 16, 16, __half, wmma::row_major> fa;
                    wmma::load_matrix_sync(fa, As + ((wm * MF + i) * 16) * LDA + ksx * 16, LDA);
#pragma unroll
                    for (int j = 0; j < 2; j++)
                        wmma::mma_sync(acc[i][j], fa, fb[j], acc[i][j]);
                }
            }
            if (cc + 1 < NCP) {
                store_st(st ^ 1, nva, nwv);
                __syncthreads();
            }
        }
    }
    __syncthreads();
#pragma unroll
    for (int i = 0; i < MF; i++)
#pragma unroll
        for (int j = 0; j < 2; j++)
            wmma::store_matrix_sync(Cs + ((wm * MF + i) * 16) * LDC + wn * 32 + j * 16,
                                    acc[i][j], LDC, wmma::mem_row_major);
    __syncthreads();
    if constexpr (KS > 1) {
        int r2 = tid / TPR, ch0 = (tid % TPR) * (COUT / TPR);
        long base = (long)part * 1048576 + (long)(m0 + r2) * COUT + ch0;
#pragma unroll
        for (int c = 0; c < COUT / TPR; c += 4)
            *(float4*)(pout + base + c) = *(const float4*)&Cs[r2 * LDC + ch0 + c];
    } else {
        int r2 = tid / TPR, ch0 = (tid % TPR) * (COUT / TPR);
        long base = (long)(m0 + r2) * COUT + ch0;
#pragma unroll
        for (int c = 0; c < COUT / TPR; c += 4) {
            float v0 = fmaxf(Cs[r2 * LDC + ch0 + c]     + bias[ch0 + c], 0.f);
            float v1 = fmaxf(Cs[r2 * LDC + ch0 + c + 1] + bias[ch0 + c + 1], 0.f);
            float v2 = fmaxf(Cs[r2 * LDC + ch0 + c + 2] + bias[ch0 + c + 2], 0.f);
            float v3 = fmaxf(Cs[r2 * LDC + ch0 + c + 3] + bias[ch0 + c + 3], 0.f);
            __half2 p0 = __floats2half2_rn(v0, v1);
            __half2 p1 = __floats2half2_rn(v2, v3);
            uint2 p;
            p.x = *reinterpret_cast<uint32_t*>(&p0);
            p.y = *reinterpret_cast<uint32_t*>(&p1);
            *(uint2*)(aout + base + c) = p;
        }
    }
}

// L6 split-K reduce.
__global__ void l6_red(const float* __restrict__ scr, const float* __restrict__ bias,
                       __half* __restrict__ outp) {
    int i = (blockIdx.x * 256 + threadIdx.x) * 4;
    float4 s = *(const float4*)(scr + i);
#pragma unroll
    for (int p = 1; p < 4; p++) {
        float4 v = *(const float4*)(scr + (long)p * 1048576 + i);
        s.x += v.x; s.y += v.y; s.z += v.z; s.w += v.w;
    }
    int n = i & 127;
    float4 b = *(const float4*)(bias + n);
    s.x = fmaxf(s.x + b.x, 0.f);
    s.y = fmaxf(s.y + b.y, 0.f);
    s.z = fmaxf(s.z + b.z, 0.f);
    s.w = fmaxf(s.w + b.w, 0.f);
    __half2 p0 = __floats2half2_rn(s.x, s.y);
    __half2 p1 = __floats2half2_rn(s.z, s.w);
    uint2 p;
    p.x = *reinterpret_cast<uint32_t*>(&p0);
    p.y = *reinterpret_cast<uint32_t*>(&p1);
    *(uint2*)(outp + i) = p;
}

// ============================================================================
// wmma GEMM fp16 2-term, fp32 out, BK=32 double-buffered.  CTA: 64 x 128.
// ============================================================================
template <int NTOT, int K, bool RELU>
__global__ __launch_bounds__(256) void mm_wm5(
    const __half* __restrict__ ain,
    const __half* __restrict__ whi, const __half* __restrict__ wlo,
    const float* __restrict__ bias, float* __restrict__ out) {
    constexpr int NC = K / 32;
    constexpr int LDA = 40, LDB = 136, LDC = 132;
    constexpr int ASZ = 64 * LDA, BSZ = 32 * LDB;
    constexpr int SST = ASZ + 2 * BSZ;
    constexpr int LOADSZ = 2 * SST * 2;
    constexpr int CSZ = 64 * LDC * 4;
    constexpr int SMSZ = (LOADSZ > CSZ) ? LOADSZ : CSZ;

    __shared__ __align__(16) char sm[SMSZ];
    __half* smb = (__half*)sm;
    float* Cs = (float*)sm;

    int tid = threadIdx.x, wid = tid >> 5;
    int m0 = blockIdx.x * 64, n0 = blockIdx.y * 128;
    int r = tid >> 2, h = (tid & 3) * 8;
    long mrow = m0 + r;
    int kb = tid >> 4, nb = (tid & 15) * 8;

    auto lda_r = [&](int c, uint4& va) {
        va = *(const uint4*)(ain + mrow * K + c * 32 + h);
    };
    auto ldb_r = [&](int c, uint4* w) {
        long g0 = (long)(c * 32 + kb) * NTOT + n0 + nb;
        long g1 = (long)(c * 32 + kb + 16) * NTOT + n0 + nb;
        w[0] = *(const uint4*)(whi + g0);
        w[1] = *(const uint4*)(whi + g1);
        w[2] = *(const uint4*)(wlo + g0);
        w[3] = *(const uint4*)(wlo + g1);
    };
    auto store_st = [&](int st, const uint4& va, const uint4* w) {
        __half* As = smb + st * SST;
        __half* BsH = As + ASZ;
        __half* BsL = BsH + BSZ;
        *(uint4*)(As + r * LDA + h) = va;
        *(uint4*)(BsH + kb * LDB + nb) = w[0];
        *(uint4*)(BsH + (kb + 16) * LDB + nb) = w[1];
        *(uint4*)(BsL + kb * LDB + nb) = w[2];
        *(uint4*)(BsL + (kb + 16) * LDB + nb) = w[3];
    };

    int wm = wid >> 2, wn = wid & 3;
    wmma::fragment<wmma::accumulator, 16, 16, 16, float> acc[2][2];
#pragma unroll
    for (int i = 0; i < 2; i++)
#pragma unroll
        for (int j = 0; j < 2; j++) wmma::fill_fragment(acc[i][j], 0.f);

    uint4 va, nva = make_uint4(0, 0, 0, 0);
    uint4 w[4], nw[4];
#pragma unroll
    for (int j = 0; j < 4; j++) { w[j] = make_uint4(0, 0, 0, 0); nw[j] = w[j]; }
    lda_r(0, va); ldb_r(0, w);
    store_st(0, va, w);
    __syncthreads();
    for (int c = 0; c < NC; c++) {
        int st = c & 1;
        if (c + 1 < NC) { lda_r(c + 1, nva); ldb_r(c + 1, nw); }
        const __half* As = smb + st * SST;
        const __half* BsH = As + ASZ;
        const __half* BsL = BsH + BSZ;
#pragma unroll
        for (int ks = 0; ks < 2; ks++) {
            wmma::fragment<wmma::matrix_b, 16, 16, 16, __half, wmma::row_major> fbh[2], fbl[2];
#pragma unroll
            for (int j = 0; j < 2; j++) {
                wmma::load_matrix_sync(fbh[j], BsH + (ks * 16) * LDB + wn * 32 + j * 16, LDB);
                wmma::load_matrix_sync(fbl[j], BsL + (ks * 16) * LDB + wn * 32 + j * 16, LDB);
            }
#pragma unroll
            for (int i = 0; i < 2; i++) {
                wmma::fragment<wmma::matrix_a, 16, 16, 16, __half, wmma::row_major> fa;
                wmma::load_matrix_sync(fa, As + ((wm * 2 + i) * 16) * LDA + ks * 16, LDA);
#pragma unroll
                for (int j = 0; j < 2; j++) {
                    wmma::mma_sync(acc[i][j], fa, fbh[j], acc[i][j]);
                    wmma::mma_sync(acc[i][j], fa, fbl[j], acc[i][j]);
                }
            }
        }
        if (c + 1 < NC) {
            store_st(st ^ 1, nva, nw);
            __syncthreads();
        }
    }
    __syncthreads();
#pragma unroll
    for (int i = 0; i < 2; i++)
#pragma unroll
        for (int j = 0; j < 2; j++)
            wmma::store_matrix_sync(Cs + ((wm * 2 + i) * 16) * LDC + wn * 32 + j * 16,
                                    acc[i][j], LDC, wmma::mem_row_major);
    __syncthreads();
    {
        int r2 = tid >> 2, ch0 = (tid & 3) * 32;
        long base = (long)(m0 + r2) * NTOT + n0 + ch0;
#pragma unroll
        for (int c = 0; c < 32; c += 4) {
            float4 v;
            v.x = Cs[r2 * LDC + ch0 + c]     + bias[n0 + ch0 + c];
            v.y = Cs[r2 * LDC + ch0 + c + 1] + bias[n0 + ch0 + c + 1];
            v.z = Cs[r2 * LDC + ch0 + c + 2] + bias[n0 + ch0 + c + 2];
            v.w = Cs[r2 * LDC + ch0 + c + 3] + bias[n0 + ch0 + c + 3];
            if (RELU) {
                v.x = fmaxf(v.x, 0.f); v.y = fmaxf(v.y, 0.f);
                v.z = fmaxf(v.z, 0.f); v.w = fmaxf(v.w, 0.f);
            }
            *(float4*)(out + base + c) = v;
        }
    }
}

// ============================================================================
// Persistent LSTM: 64 CTAs x 256 threads (K-split 2), all 32 steps.
// ============================================================================
__global__ __launch_bounds__(256) void lstm_all(
    const float* __restrict__ xg, const float* __restrict__ wthh,
    const float* __restrict__ done, float* __restrict__ hbuf0,
    float* __restrict__ hbuf1, float* __restrict__ cbuf,
    __half* __restrict__ hs, int* __restrict__ bar) {
    extern __shared__ float smf[];
    float* Ws  = smf;
    float* shh = Ws + 512 * 36;
    float* red = shh + 16 * 520;

    int tid = threadIdx.x;
    int n0 = blockIdx.x * 32;

#pragma unroll
    for (int i = 0; i < 16; i++) {
        int f = i * 256 + tid;
        int k = f >> 3, cc = (f & 7) * 4;
        *(float4*)&Ws[k * 36 + cc] = *(const float4*)&wthh[(long)k * 2048 + n0 + cc];
    }

    int ks = tid >> 7;
    int lt = tid & 127;
    int tx = lt & 7, ty = lt >> 3;
    int u = (n0 >> 2) + tx;
    float creg = 0.f;
    if (ks == 0) creg = cbuf[ty * 512 + u];

    for (int t = 0; t < 32; t++) {
        const float* hin = (t & 1) ? hbuf1 : hbuf0;
        float* hout = (t & 1) ? hbuf0 : hbuf1;
#pragma unroll
        for (int i = 0; i < 8; i++) {
            int idx4 = i * 256 + tid;
            int b = idx4 >> 7, q = idx4 & 127;
            float keep = 1.f - done[t * 16 + b];
            float4 v = ((const float4*)hin)[idx4];
            v.x *= keep; v.y *= keep; v.z *= keep; v.w *= keep;
            *(float4*)&shh[b * 520 + q * 4] = v;
        }
        __syncthreads();
        float a0 = 0.f, a1 = 0.f, a2 = 0.f, a3 = 0.f;
        int kbase = ks * 256;
        const float* hrow = shh + ty * 520 + kbase;
        const float* wbase = Ws + kbase * 36 + tx * 4;
#pragma unroll 8
        for (int kk = 0; kk < 256; kk++) {
            float a = hrow[kk];
            float4 w = *(const float4*)(wbase + kk * 36);
            a0 += a * w.x; a1 += a * w.y; a2 += a * w.z; a3 += a * w.w;
        }
        if (ks == 1) {
            *(float4*)&red[lt * 4] = make_float4(a0, a1, a2, a3);
        }
        __syncthreads();
        if (ks == 0) {
            float4 rr = *(const float4*)&red[lt * 4];
            float4 xv = *(const float4*)&xg[(long)(t * 16 + ty) * 2048 + n0 + tx * 4];
            float ig = a0 + rr.x + xv.x;
            float fg = a1 + rr.y + xv.y;
            float gg = a2 + rr.z + xv.z;
            float og = a3 + rr.w + xv.w;
            float keep = 1.f - done[t * 16 + ty];
            float cold = creg * keep;
            float si = 1.f / (1.f + expf(-ig));
            float sf = 1.f / (1.f + expf(-fg));
            float so = 1.f / (1.f + expf(-og));
            float cn = sf * cold + si * tanhf(gg);
            float hn = so * tanhf(cn);
            creg = cn;
            hout[ty * 512 + u] = hn;
            hs[(long)(t * 16 + ty) * 512 + u] = __float2half_rn(hn);
        }
        __threadfence();
        __syncthreads();
        if (tid == 0) {
            atomicAdd(bar, 1);
            int target = 64 * (t + 1);
            while (atomicAdd(bar, 0) < target) __nanosleep(64);
        }
        __syncthreads();
        __threadfence();
    }
    if (ks == 0) cbuf[ty * 512 + u] = creg;
}

// ---------------------------------------------------------------------------
extern "C" void kernel_launch(void* const* d_in, const int* in_sizes, int n_in,
                              void* d_out, int out_size) {
    (void)in_sizes; (void)n_in; (void)out_size;
    __half* hh = nullptr;
    float* fa = nullptr;
    cudaGetSymbolAddress((void**)&hh, g_hh);
    cudaGetSymbolAddress((void**)&fa, g_f);

    const float* x    = (const float*)d_in[0];
    const float* done = (const float*)d_in[1];
    const float* h0   = (const float*)d_in[2];
    const float* c0   = (const float*)d_in[3];
    const float* w11  = (const float*)d_in[4];
    const float* b11  = (const float*)d_in[5];
    const float* w12  = (const float*)d_in[6];
    const float* b12  = (const float*)d_in[7];
    const float* w21  = (const float*)d_in[8];
    const float* b21  = (const float*)d_in[9];
    const float* w22  = (const float*)d_in[10];
    const float* b22  = (const float*)d_in[11];
    const float* w31  = (const float*)d_in[12];
    const float* b31  = (const float*)d_in[13];
    const float* w32  = (const float*)d_in[14];
    const float* b32  = (const float*)d_in[15];
    const float* W_ih = (const float*)d_in[16];
    const float* W_hh = (const float*)d_in[17];
    const float* b_ih = (const float*)d_in[18];
    const float* b_hh = (const float*)d_in[19];
    const float* Wf   = (const float*)d_in[20];
    const float* bf   = (const float*)d_in[21];
    float* out = (float*)d_out;

    cudaFuncSetAttribute(ihw_prep_t, cudaFuncAttributeMaxDynamicSharedMemorySize, 69632);
    cudaFuncSetAttribute(lstm_all, cudaFuncAttributeMaxDynamicSharedMemorySize, 110592);

    // ---- prep ----
    prep_x_convw<<<16580, 256>>>(x, hh + O_X, w11, w12, w21, w22, w31, w32,
                                 hh + O_W1, hh + O_W2, hh + O_W3,
                                 hh + O_W4, hh + O_W5, hh + O_W6);
    ihw_prep_t<<<dim3(16, 16), 256, 69632>>>(W_ih, hh + O_WIHH, hh + O_WIHL);
    misc_prep<<<5128, 256>>>(Wf, hh + O_WFH, hh + O_WFL, W_hh, fa + F_WTHH,
                             b_ih, b_hh, fa + F_BG);
    cudaMemcpyAsync(fa + F_H0, h0, 8192 * sizeof(float), cudaMemcpyDeviceToDevice, 0);
    cudaMemcpyAsync(fa + F_C,  c0, 8192 * sizeof(float), cudaMemcpyDeviceToDevice, 0);
    cudaMemsetAsync(fa + F_BAR, 0, sizeof(int), 0);

    // ---- conv stack ----
    conv_wm8<4, 32, 7, 32, 32, 1, 1><<<24576, 256>>>(hh + O_X, hh + O_W1, b11, hh + O_A1, nullptr);
    conv_wm8<32, 32, 6, 32, 32, 2, 1><<<5120, 256>>>(hh + O_A1, hh + O_W2, b12, hh + O_A2, nullptr);
    conv_wm8<32, 64, 5, 16, 16, 1, 1><<<4096, 256>>>(hh + O_A2, hh + O_W3, b21, hh + O_A3, nullptr);
    conv_wm8<64, 64, 4, 16, 16, 2, 1><<<768, 256>>>(hh + O_A3, hh + O_W4, b22, hh + O_A4, nullptr);
    conv_wm8<64, 128, 3, 8, 8, 1, 1><<<1024, 256>>>(hh + O_A4, hh + O_W5, b31, hh + O_A5, nullptr);
    conv_wm8<128, 128, 2, 8, 8, 2, 4><<<dim3(128, 4), 256>>>(hh + O_A5, hh + O_W6, b32, nullptr, fa + F_SCR);
    l6_red<<<1024, 256>>>(fa + F_SCR, b32, hh + O_F);

    // ---- LSTM input GEMM (BK=32) ----
    mm_wm5<2048, 2048, false><<<dim3(8, 16), 256>>>(
        hh + O_F, hh + O_WIHH, hh + O_WIHL, fa + F_BG, fa + F_XG);

    // ---- persistent LSTM ----
    lstm_all<<<64, 256, 110592>>>(fa + F_XG, fa + F_WTHH, done,
                                  fa + F_H0, fa + F_H1, fa + F_C,
                                  hh + O_HS, (int*)(fa + F_BAR));

    // ---- final FC + relu into d_out (BK=32) ----
    mm_wm5<512, 512, true><<<dim3(8, 4), 256>>>(
        hh + O_HS, hh + O_WFH, hh + O_WFL, bf, out);

    // ---- hT, cT ----
    cudaMemcpyAsync(out + 262144, fa + F_H0, 8192 * sizeof(float),
                    cudaMemcpyDeviceToDevice, 0);
    cudaMemcpyAsync(out + 270336, fa + F_C, 8192 * sizeof(float),
                    cudaMemcpyDeviceToDevice, 0);
}

// round 17
// speedup vs baseline: 1.1169x; 1.0018x over previous
#include <cuda_runtime.h>
#include <cuda_fp16.h>
#include <mma.h>
#include <stdint.h>

using namespace nvcuda;

// ============================================================================
// CNN(6x conv3d) + LSTM(32) + FC.   (R14 proven base + merged prep launches)
// Conv: wmma fp16 single-term, BK=32 double-buffered; L1-L3 fully unrolled
//       mainloop with compile-time tap geometry; L6 split-K=4.
// IH/FC: fp16 2-term (weights 21-bit), BK=32 double-buffered.
// LSTM: persistent kernel, W_hh resident in smem, grid barrier between steps.
// Activations NDHWC fp16.  Weights k-major.
// ============================================================================

__device__ __forceinline__ void splitw(float v, __half& h, __half& l) {
    h = __float2half_rn(v);
    l = __float2half_rn(v - __half2float(h));
}

template <int I> struct IC { static constexpr int v = I; };
template <int N, int I = 0, typename F>
__device__ __forceinline__ void sfor(F&& f) {
    if constexpr (I < N) { f(IC<I>{}); sfor<N, I + 1>(f); }
}
__host__ __device__ constexpr int tkd(int t) { return t >= 9 ? 1 : 0; }
__host__ __device__ constexpr int tkh(int t) { return (t - 9 * tkd(t)) / 3; }
__host__ __device__ constexpr int tkw(int t) { return (t - 9 * tkd(t)) % 3; }

// Gather 4 consecutive taps (CIN==4) from fp16 activations, compile-time geometry.
template <int T0, int HIN, int WIN>
__device__ __forceinline__ void g4(uint2* tv, const __half* __restrict__ ain, long xb,
                                   bool ihok0, bool ihok2, bool iwok0, bool iwok2) {
    sfor<4>([&](auto J) {
        constexpr int TAP = T0 + decltype(J)::v;
        if constexpr (TAP < 18) {
            constexpr int kd = tkd(TAP), kh = tkh(TAP), kw = tkw(TAP);
            constexpr int DEL = (kd * HIN * WIN + (kh - 1) * WIN + (kw - 1)) * 4;
            bool p = (kh == 0 ? ihok0 : (kh == 2 ? ihok2 : true)) &&
                     (kw == 0 ? iwok0 : (kw == 2 ? iwok2 : true));
            if (p) tv[decltype(J)::v] = *(const uint2*)(ain + xb + DEL);
        }
    });
}

// ---- fp16 arena ----
#define O_A1  0LL
#define O_A2  100663296LL
#define O_A3  121634816LL
#define O_A4  155189248LL
#define O_A5  161480704LL
#define O_F   169869312LL
#define O_W1  170917888LL
#define O_W2  170923008LL
#define O_W3  170959872LL
#define O_W4  171033600LL
#define O_W5  171181056LL
#define O_W6  171475968LL
#define O_WIHH 172065792LL
#define O_WIHL 176260096LL
#define O_WFH 180454400LL
#define O_WFL 180716544LL
#define O_X   180978688LL
#define O_HS  195658752LL
#define H_TOTAL 195920896LL
__device__ __half g_hh[H_TOTAL];

// ---- fp32 arena ----
#define F_XG   0LL
#define F_WTHH 1048576LL
#define F_BG   2097152LL
#define F_H0   2099200LL
#define F_H1   2107392LL
#define F_C    2115584LL
#define F_BAR  2123776LL
#define F_SCR  2123780LL
#define F_TOTAL 6318084LL
__device__ float g_f[F_TOTAL];

// ---- prep: xprep + convw + wf/whh/bias merged into ONE launch ----
__global__ void prep_all(const float* __restrict__ x, __half* __restrict__ xo,
                         const float* s1, const float* s2, const float* s3,
                         const float* s4, const float* s5, const float* s6,
                         __half* d1, __half* d2, __half* d3,
                         __half* d4, __half* d5, __half* d6,
                         const float* __restrict__ Wf, __half* __restrict__ wfh,
                         __half* __restrict__ wfl,
                         const float* __restrict__ Whh, float* __restrict__ wthh,
                         const float* __restrict__ bi, const float* __restrict__ bh2,
                         float* __restrict__ bg) {
    if (blockIdx.x < 14336) {
        long i = ((long)blockIdx.x * blockDim.x + threadIdx.x) * 4;
        float4 v = *(const float4*)(x + i);
        __half2 a = __floats2half2_rn(v.x, v.y);
        __half2 b = __floats2half2_rn(v.z, v.w);
        uint2 p;
        p.x = *reinterpret_cast<uint32_t*>(&a);
        p.y = *reinterpret_cast<uint32_t*>(&b);
        *(uint2*)(xo + i) = p;
        return;
    }
    if (blockIdx.x < 16580) {
        int i = (blockIdx.x - 14336) * blockDim.x + threadIdx.x;
        const float* src; __half* dst;
        int CIN, COUT, Kpad; float scale = 1.f;
        if (i < 3072)        { src = s1; dst = d1; CIN = 4;   COUT = 32;  Kpad = 96;   scale = 1.f / 255.f; }
        else if (i < 21504)  { src = s2; dst = d2; CIN = 32;  COUT = 32;  Kpad = 576;  i -= 3072; }
        else if (i < 58368)  { src = s3; dst = d3; CIN = 32;  COUT = 64;  Kpad = 576;  i -= 21504; }
        else if (i < 132096) { src = s4; dst = d4; CIN = 64;  COUT = 64;  Kpad = 1152; i -= 58368; }
        else if (i < 279552) { src = s5; dst = d5; CIN = 64;  COUT = 128; Kpad = 1152; i -= 132096; }
        else if (i < 574464) { src = s6; dst = d6; CIN = 128; COUT = 128; Kpad = 2304; i -= 279552; }
        else return;
        int co = i / Kpad, kk = i % Kpad;
        float v = 0.f;
        if (kk < CIN * 18) {
            int cin = kk % CIN, tap = kk / CIN;
            v = src[(co * CIN + cin) * 18 + tap] * scale;
        }
        dst[(long)kk * COUT + co] = __float2half_rn(v);
        return;
    }
    int i = (blockIdx.x - 16580) * blockDim.x + threadIdx.x;
    if (i < 262144) {
        int n = i >> 9, k = i & 511;
        __half h, l;
        splitw(Wf[i], h, l);
        long o = (long)k * 512 + n;
        wfh[o] = h;
        wfl[o] = l;
    } else if (i < 262144 + 1048576) {
        int j = i - 262144;
        int r = j >> 9, k = j & 511;
        int g = r >> 9, u = r & 511;
        wthh[k * 2048 + (u << 2) + g] = Whh[j];
    } else if (i < 262144 + 1048576 + 2048) {
        int j = i - 262144 - 1048576;
        int g = j >> 9, u = j & 511;
        bg[(u << 2) + g] = bi[j] + bh2[j];
    }
}
__global__ void ihw_prep_t(const float* __restrict__ src,
                           __half* __restrict__ dh, __half* __restrict__ dl) {
    extern __shared__ __half ts[];
    __half* TH = ts;
    __half* TL = ts + 128 * 136;
    int tid = threadIdx.x;
    int kb = blockIdx.x * 128, nbv = blockIdx.y * 128;
    {
        int n2 = nbv + (tid >> 1);
        int g = n2 & 3, u = n2 >> 2;
        const float* srow = src + (long)(g * 512 + u) * 2048 + kb + (tid & 1) * 64;
        int klo = (tid & 1) * 64, col = tid >> 1;
#pragma unroll
        for (int q = 0; q < 16; q++) {
            float4 v = *(const float4*)(srow + q * 4);
            float vv[4] = {v.x, v.y, v.z, v.w};
#pragma unroll
            for (int e = 0; e < 4; e++) {
                __half h, l;
                splitw(vv[e], h, l);
                TH[(klo + q * 4 + e) * 136 + col] = h;
                TL[(klo + q * 4 + e) * 136 + col] = l;
            }
        }
    }
    __syncthreads();
    {
        int kl = tid >> 1, nh = (tid & 1) * 64;
        int cl = kl >> 4, sp = kl & 15;
        int k2 = sp * 128 + (kb >> 4) + cl;
        long base = (long)k2 * 2048 + nbv + nh;
#pragma unroll
        for (int q = 0; q < 8; q++) {
            *(uint4*)(dh + base + q * 8) = *(const uint4*)(TH + kl * 136 + nh + q * 8);
            *(uint4*)(dl + base + q * 8) = *(const uint4*)(TL + kl * 136 + nh + q * 8);
        }
    }
}

// ============================================================================
// wmma implicit-GEMM conv.  NC<=18 && KS==1: fully-unrolled mainloop with
// compile-time tap geometry.  Else: runtime loop (L4/L5/L6).
// ============================================================================
template <int CIN, int COUT, int DIN, int HIN, int WIN, int S, int KS>
__global__ __launch_bounds__(256) void conv_wm8(
    const __half* __restrict__ ain, const __half* __restrict__ wgt,
    const float* __restrict__ bias, __half* __restrict__ aout,
    float* __restrict__ pout) {
    constexpr int DOUT = DIN - 1;
    constexpr int HOUT = (S == 1) ? HIN : HIN / 2;
    constexpr int WOUT = (S == 1) ? WIN : WIN / 2;
    constexpr int Kpad = (CIN == 4) ? 96 : CIN * 18;
    constexpr int NC = Kpad / 32;
    constexpr int NCP = NC / KS;
    constexpr int BM = (COUT >= 128) ? 64 : 128;
    constexpr int TPR = 256 / BM;
    constexpr int HS = 32 / TPR;
    constexpr int WN = (COUT >= 128) ? 4 : (COUT / 32);
    constexpr int WM = 8 / WN, MF = BM / (WM * 16);
    constexpr int LDA = 40, LDB = COUT + 8, LDC = COUT + 4;
    constexpr int ASZ = BM * LDA, BSZ = 32 * LDB;
    constexpr int SST = ASZ + BSZ;
    constexpr int L2C = (CIN == 32) ? 5 : ((CIN == 64) ? 6 : 7);
    constexpr int LOADSZ = 2 * SST * 2;
    constexpr int CSZ = BM * LDC * 4;
    constexpr int SMSZ = (LOADSZ > CSZ) ? LOADSZ : CSZ;
    constexpr bool UNROLLED = (KS == 1) && (NC <= 18);

    __shared__ __align__(16) char sm[SMSZ];
    __half* smb = (__half*)sm;
    float* Cs = (float*)sm;

    int tid = threadIdx.x, wid = tid >> 5;
    int m0 = blockIdx.x * BM;
    int part = blockIdx.y;
    int c0 = part * NCP;
    int r = tid / TPR;
    int h = (tid % TPR) * HS;
    int m = m0 + r;
    int ow = m % WOUT; int t1 = m / WOUT;
    int oh = t1 % HOUT; int t2 = t1 / HOUT;
    int od = t2 % DOUT; int bb = t2 / DOUT;

    constexpr int TPK = COUT / 8;
    int kb = tid / TPK, nb = (tid % TPK) * 8;
    bool bact = kb < 32;

    long xb = ((((long)bb * DIN + od) * HIN + oh * S) * WIN + ow * S) * CIN;
    bool ihok0 = oh * S >= 1, ihok2 = oh * S + 1 < HIN;
    bool iwok0 = ow * S >= 1, iwok2 = ow * S + 1 < WIN;

    auto ldb_r = [&](int c, uint4* wv) {
        if constexpr (COUT == 128) {
            wv[0] = *(const uint4*)(wgt + (long)(c * 32 + kb) * COUT + nb);
            wv[1] = *(const uint4*)(wgt + (long)(c * 32 + kb + 16) * COUT + nb);
        } else {
            if (bact) wv[0] = *(const uint4*)(wgt + (long)(c * 32 + kb) * COUT + nb);
        }
    };
    auto store_st = [&](int st, const uint4* va, const uint4* wv) {
        __half* As = smb + st * SST;
        __half* Bs = As + ASZ;
        *(uint4*)(As + r * LDA + h) = va[0];
        if constexpr (TPR == 2) *(uint4*)(As + r * LDA + h + 8) = va[1];
        if constexpr (COUT == 128) {
            *(uint4*)(Bs + kb * LDB + nb) = wv[0];
            *(uint4*)(Bs + (kb + 16) * LDB + nb) = wv[1];
        } else {
            if (bact) *(uint4*)(Bs + kb * LDB + nb) = wv[0];
        }
    };

    int wm = wid / WN, wn = wid % WN;
    wmma::fragment<wmma::accumulator, 16, 16, 16, float> acc[MF][2];
#pragma unroll
    for (int i = 0; i < MF; i++)
#pragma unroll
        for (int j = 0; j < 2; j++) wmma::fill_fragment(acc[i][j], 0.f);

    uint4 va[2], wv[2], nva[2], nwv[2];
    va[0] = va[1] = wv[0] = wv[1] = make_uint4(0, 0, 0, 0);
    nva[0] = nva[1] = nwv[0] = nwv[1] = va[0];

    if constexpr (UNROLLED) {
        auto gather = [&](auto C, uint4* dst) {
            constexpr int c = decltype(C)::v;
            if constexpr (CIN == 4) {
                uint2 tv[4];
                tv[0] = tv[1] = tv[2] = tv[3] = make_uint2(0u, 0u);
                if (h == 0) g4<c * 8 + 0, HIN, WIN>(tv, ain, xb, ihok0, ihok2, iwok0, iwok2);
                else        g4<c * 8 + 4, HIN, WIN>(tv, ain, xb, ihok0, ihok2, iwok0, iwok2);
                dst[0] = make_uint4(tv[0].x, tv[0].y, tv[1].x, tv[1].y);
                dst[1] = make_uint4(tv[2].x, tv[2].y, tv[3].x, tv[3].y);
            } else {
                constexpr int tap = (c * 32) / CIN;
                constexpr int kd = tkd(tap), kh = tkh(tap), kw = tkw(tap);
                constexpr int cinb = 32 * (c % (CIN / 32));
                constexpr long DEL = (long)(kd * HIN * WIN + (kh - 1) * WIN + (kw - 1)) * CIN + cinb;
                dst[0] = make_uint4(0u, 0u, 0u, 0u);
                dst[1] = dst[0];
                bool p = (kh == 0 ? ihok0 : (kh == 2 ? ihok2 : true)) &&
                         (kw == 0 ? iwok0 : (kw == 2 ? iwok2 : true));
                if (p) {
                    const __half* src = ain + xb + DEL + h;
                    dst[0] = *(const uint4*)(src);
                    if constexpr (TPR == 2) dst[1] = *(const uint4*)(src + 8);
                }
            }
        };
        gather(IC<0>{}, va); ldb_r(0, wv);
        store_st(0, va, wv);
        __syncthreads();
        sfor<NCP>([&](auto CC) {
            constexpr int cc = decltype(CC)::v;
            constexpr int st = cc & 1;
            if constexpr (cc + 1 < NCP) { gather(IC<cc + 1>{}, nva); ldb_r(cc + 1, nwv); }
            const __half* As = smb + st * SST;
            const __half* Bs = As + ASZ;
            constexpr int KSN = (CIN == 4 && cc == 2) ? 1 : 2;   // skip all-zero pad kstep
#pragma unroll
            for (int ksx = 0; ksx < KSN; ksx++) {
                wmma::fragment<wmma::matrix_b, 16, 16, 16, __half, wmma::row_major> fb[2];
#pragma unroll
                for (int j = 0; j < 2; j++)
                    wmma::load_matrix_sync(fb[j], Bs + (ksx * 16) * LDB + wn * 32 + j * 16, LDB);
#pragma unroll
                for (int i = 0; i < MF; i++) {
                    wmma::fragment<wmma::matrix_a, 16, 16, 16, __half, wmma::row_major> fa;
                    wmma::load_matrix_sync(fa, As + ((wm * MF + i) * 16) * LDA + ksx * 16, LDA);
#pragma unroll
                    for (int j = 0; j < 2; j++)
                        wmma::mma_sync(acc[i][j], fa, fb[j], acc[i][j]);
                }
            }
            if constexpr (cc + 1 < NCP) {
                store_st(st ^ 1, nva, nwv);
                __syncthreads();
            }
        });
    } else {
        auto lda_r = [&](int c, uint4* dst) {
            dst[0] = make_uint4(0u, 0u, 0u, 0u);
            dst[1] = dst[0];
            int kk = c * 32 + h;
            int tap = kk >> L2C, cin = kk & (CIN - 1);
            int kd = (tap >= 9) ? 1 : 0; int rr = tap - 9 * kd;
            int kh = rr / 3, kw = rr - 3 * kh;
            int ih = oh * S - 1 + kh, iw = ow * S - 1 + kw;
            if ((unsigned)ih < (unsigned)HIN && (unsigned)iw < (unsigned)WIN) {
                long g = ((((long)bb * DIN + od + kd) * HIN + ih) * WIN + iw) * CIN + cin;
                dst[0] = *(const uint4*)(ain + g);
                if constexpr (TPR == 2) dst[1] = *(const uint4*)(ain + g + 8);
            }
        };
        lda_r(c0, va); ldb_r(c0, wv);
        store_st(0, va, wv);
        __syncthreads();
        for (int cc = 0; cc < NCP; cc++) {
            int c = c0 + cc;
            int st = cc & 1;
            if (cc + 1 < NCP) { lda_r(c + 1, nva); ldb_r(c + 1, nwv); }
            const __half* As = smb + st * SST;
            const __half* Bs = As + ASZ;
#pragma unroll
            for (int ksx = 0; ksx < 2; ksx++) {
                wmma::fragment<wmma::matrix_b, 16, 16, 16, __half, wmma::row_major> fb[2];
#pragma unroll
                for (int j = 0; j < 2; j++)
                    wmma::load_matrix_sync(fb[j], Bs + (ksx * 16) * LDB + wn * 32 + j * 16, LDB);
#pragma unroll
                for (int i = 0; i < MF; i++) {
                    wmma::fragment<wmma::matrix_a, 16, 16, 16, __half, wmma::row_major> fa;
                    wmma::load_matrix_sync(fa, As + ((wm * MF + i) * 16) * LDA + ksx * 16, LDA);
#pragma unroll
                    for (int j = 0; j < 2; j++)
                        wmma::mma_sync(acc[i][j], fa, fb[j], acc[i][j]);
                }
            }
            if (cc + 1 < NCP) {
                store_st(st ^ 1, nva, nwv);
                __syncthreads();
            }
        }
    }
    __syncthreads();
#pragma unroll
    for (int i = 0; i < MF; i++)
#pragma unroll
        for (int j = 0; j < 2; j++)
            wmma::store_matrix_sync(Cs + ((wm * MF + i) * 16) * LDC + wn * 32 + j * 16,
                                    acc[i][j], LDC, wmma::mem_row_major);
    __syncthreads();
    if constexpr (KS > 1) {
        int r2 = tid / TPR, ch0 = (tid % TPR) * (COUT / TPR);
        long base = (long)part * 1048576 + (long)(m0 + r2) * COUT + ch0;
#pragma unroll
        for (int c = 0; c < COUT / TPR; c += 4)
            *(float4*)(pout + base + c) = *(const float4*)&Cs[r2 * LDC + ch0 + c];
    } else {
        int r2 = tid / TPR, ch0 = (tid % TPR) * (COUT / TPR);
        long base = (long)(m0 + r2) * COUT + ch0;
#pragma unroll
        for (int c = 0; c < COUT / TPR; c += 4) {
            float v0 = fmaxf(Cs[r2 * LDC + ch0 + c]     + bias[ch0 + c], 0.f);
            float v1 = fmaxf(Cs[r2 * LDC + ch0 + c + 1] + bias[ch0 + c + 1], 0.f);
            float v2 = fmaxf(Cs[r2 * LDC + ch0 + c + 2] + bias[ch0 + c + 2], 0.f);
            float v3 = fmaxf(Cs[r2 * LDC + ch0 + c + 3] + bias[ch0 + c + 3], 0.f);
            __half2 p0 = __floats2half2_rn(v0, v1);
            __half2 p1 = __floats2half2_rn(v2, v3);
            uint2 p;
            p.x = *reinterpret_cast<uint32_t*>(&p0);
            p.y = *reinterpret_cast<uint32_t*>(&p1);
            *(uint2*)(aout + base + c) = p;
        }
    }
}

// L6 split-K reduce.
__global__ void l6_red(const float* __restrict__ scr, const float* __restrict__ bias,
                       __half* __restrict__ outp) {
    int i = (blockIdx.x * 256 + threadIdx.x) * 4;
    float4 s = *(const float4*)(scr + i);
#pragma unroll
    for (int p = 1; p < 4; p++) {
        float4 v = *(const float4*)(scr + (long)p * 1048576 + i);
        s.x += v.x; s.y += v.y; s.z += v.z; s.w += v.w;
    }
    int n = i & 127;
    float4 b = *(const float4*)(bias + n);
    s.x = fmaxf(s.x + b.x, 0.f);
    s.y = fmaxf(s.y + b.y, 0.f);
    s.z = fmaxf(s.z + b.z, 0.f);
    s.w = fmaxf(s.w + b.w, 0.f);
    __half2 p0 = __floats2half2_rn(s.x, s.y);
    __half2 p1 = __floats2half2_rn(s.z, s.w);
    uint2 p;
    p.x = *reinterpret_cast<uint32_t*>(&p0);
    p.y = *reinterpret_cast<uint32_t*>(&p1);
    *(uint2*)(outp + i) = p;
}

// ============================================================================
// wmma GEMM fp16 2-term, fp32 out, BK=32 double-buffered.  CTA: 64 x 128.
// ============================================================================
template <int NTOT, int K, bool RELU>
__global__ __launch_bounds__(256) void mm_wm5(
    const __half* __restrict__ ain,
    const __half* __restrict__ whi, const __half* __restrict__ wlo,
    const float* __restrict__ bias, float* __restrict__ out) {
    constexpr int NC = K / 32;
    constexpr int LDA = 40, LDB = 136, LDC = 132;
    constexpr int ASZ = 64 * LDA, BSZ = 32 * LDB;
    constexpr int SST = ASZ + 2 * BSZ;
    constexpr int LOADSZ = 2 * SST * 2;
    constexpr int CSZ = 64 * LDC * 4;
    constexpr int SMSZ = (LOADSZ > CSZ) ? LOADSZ : CSZ;

    __shared__ __align__(16) char sm[SMSZ];
    __half* smb = (__half*)sm;
    float* Cs = (float*)sm;

    int tid = threadIdx.x, wid = tid >> 5;
    int m0 = blockIdx.x * 64, n0 = blockIdx.y * 128;
    int r = tid >> 2, h = (tid & 3) * 8;
    long mrow = m0 + r;
    int kb = tid >> 4, nb = (tid & 15) * 8;

    auto lda_r = [&](int c, uint4& va) {
        va = *(const uint4*)(ain + mrow * K + c * 32 + h);
    };
    auto ldb_r = [&](int c, uint4* w) {
        long g0 = (long)(c * 32 + kb) * NTOT + n0 + nb;
        long g1 = (long)(c * 32 + kb + 16) * NTOT + n0 + nb;
        w[0] = *(const uint4*)(whi + g0);
        w[1] = *(const uint4*)(whi + g1);
        w[2] = *(const uint4*)(wlo + g0);
        w[3] = *(const uint4*)(wlo + g1);
    };
    auto store_st = [&](int st, const uint4& va, const uint4* w) {
        __half* As = smb + st * SST;
        __half* BsH = As + ASZ;
        __half* BsL = BsH + BSZ;
        *(uint4*)(As + r * LDA + h) = va;
        *(uint4*)(BsH + kb * LDB + nb) = w[0];
        *(uint4*)(BsH + (kb + 16) * LDB + nb) = w[1];
        *(uint4*)(BsL + kb * LDB + nb) = w[2];
        *(uint4*)(BsL + (kb + 16) * LDB + nb) = w[3];
    };

    int wm = wid >> 2, wn = wid & 3;
    wmma::fragment<wmma::accumulator, 16, 16, 16, float> acc[2][2];
#pragma unroll
    for (int i = 0; i < 2; i++)
#pragma unroll
        for (int j = 0; j < 2; j++) wmma::fill_fragment(acc[i][j], 0.f);

    uint4 va, nva = make_uint4(0, 0, 0, 0);
    uint4 w[4], nw[4];
#pragma unroll
    for (int j = 0; j < 4; j++) { w[j] = make_uint4(0, 0, 0, 0); nw[j] = w[j]; }
    lda_r(0, va); ldb_r(0, w);
    store_st(0, va, w);
    __syncthreads();
    for (int c = 0; c < NC; c++) {
        int st = c & 1;
        if (c + 1 < NC) { lda_r(c + 1, nva); ldb_r(c + 1, nw); }
        const __half* As = smb + st * SST;
        const __half* BsH = As + ASZ;
        const __half* BsL = BsH + BSZ;
#pragma unroll
        for (int ks = 0; ks < 2; ks++) {
            wmma::fragment<wmma::matrix_b, 16, 16, 16, __half, wmma::row_major> fbh[2], fbl[2];
#pragma unroll
            for (int j = 0; j < 2; j++) {
                wmma::load_matrix_sync(fbh[j], BsH + (ks * 16) * LDB + wn * 32 + j * 16, LDB);
                wmma::load_matrix_sync(fbl[j], BsL + (ks * 16) * LDB + wn * 32 + j * 16, LDB);
            }
#pragma unroll
            for (int i = 0; i < 2; i++) {
                wmma::fragment<wmma::matrix_a, 16, 16, 16, __half, wmma::row_major> fa;
                wmma::load_matrix_sync(fa, As + ((wm * 2 + i) * 16) * LDA + ks * 16, LDA);
#pragma unroll
                for (int j = 0; j < 2; j++) {
                    wmma::mma_sync(acc[i][j], fa, fbh[j], acc[i][j]);
                    wmma::mma_sync(acc[i][j], fa, fbl[j], acc[i][j]);
                }
            }
        }
        if (c + 1 < NC) {
            store_st(st ^ 1, nva, nw);
            __syncthreads();
        }
    }
    __syncthreads();
#pragma unroll
    for (int i = 0; i < 2; i++)
#pragma unroll
        for (int j = 0; j < 2; j++)
            wmma::store_matrix_sync(Cs + ((wm * 2 + i) * 16) * LDC + wn * 32 + j * 16,
                                    acc[i][j], LDC, wmma::mem_row_major);
    __syncthreads();
    {
        int r2 = tid >> 2, ch0 = (tid & 3) * 32;
        long base = (long)(m0 + r2) * NTOT + n0 + ch0;
#pragma unroll
        for (int c = 0; c < 32; c += 4) {
            float4 v;
            v.x = Cs[r2 * LDC + ch0 + c]     + bias[n0 + ch0 + c];
            v.y = Cs[r2 * LDC + ch0 + c + 1] + bias[n0 + ch0 + c + 1];
            v.z = Cs[r2 * LDC + ch0 + c + 2] + bias[n0 + ch0 + c + 2];
            v.w = Cs[r2 * LDC + ch0 + c + 3] + bias[n0 + ch0 + c + 3];
            if (RELU) {
                v.x = fmaxf(v.x, 0.f); v.y = fmaxf(v.y, 0.f);
                v.z = fmaxf(v.z, 0.f); v.w = fmaxf(v.w, 0.f);
            }
            *(float4*)(out + base + c) = v;
        }
    }
}

// ============================================================================
// Persistent LSTM: 64 CTAs x 256 threads (K-split 2), all 32 steps.
// ============================================================================
__global__ __launch_bounds__(256) void lstm_all(
    const float* __restrict__ xg, const float* __restrict__ wthh,
    const float* __restrict__ done, float* __restrict__ hbuf0,
    float* __restrict__ hbuf1, float* __restrict__ cbuf,
    __half* __restrict__ hs, int* __restrict__ bar) {
    extern __shared__ float smf[];
    float* Ws  = smf;
    float* shh = Ws + 512 * 36;
    float* red = shh + 16 * 520;

    int tid = threadIdx.x;
    int n0 = blockIdx.x * 32;

#pragma unroll
    for (int i = 0; i < 16; i++) {
        int f = i * 256 + tid;
        int k = f >> 3, cc = (f & 7) * 4;
        *(float4*)&Ws[k * 36 + cc] = *(const float4*)&wthh[(long)k * 2048 + n0 + cc];
    }

    int ks = tid >> 7;
    int lt = tid & 127;
    int tx = lt & 7, ty = lt >> 3;
    int u = (n0 >> 2) + tx;
    float creg = 0.f;
    if (ks == 0) creg = cbuf[ty * 512 + u];

    for (int t = 0; t < 32; t++) {
        const float* hin = (t & 1) ? hbuf1 : hbuf0;
        float* hout = (t & 1) ? hbuf0 : hbuf1;
#pragma unroll
        for (int i = 0; i < 8; i++) {
            int idx4 = i * 256 + tid;
            int b = idx4 >> 7, q = idx4 & 127;
            float keep = 1.f - done[t * 16 + b];
            float4 v = ((const float4*)hin)[idx4];
            v.x *= keep; v.y *= keep; v.z *= keep; v.w *= keep;
            *(float4*)&shh[b * 520 + q * 4] = v;
        }
        __syncthreads();
        float a0 = 0.f, a1 = 0.f, a2 = 0.f, a3 = 0.f;
        int kbase = ks * 256;
        const float* hrow = shh + ty * 520 + kbase;
        const float* wbase = Ws + kbase * 36 + tx * 4;
#pragma unroll 8
        for (int kk = 0; kk < 256; kk++) {
            float a = hrow[kk];
            float4 w = *(const float4*)(wbase + kk * 36);
            a0 += a * w.x; a1 += a * w.y; a2 += a * w.z; a3 += a * w.w;
        }
        if (ks == 1) {
            *(float4*)&red[lt * 4] = make_float4(a0, a1, a2, a3);
        }
        __syncthreads();
        if (ks == 0) {
            float4 rr = *(const float4*)&red[lt * 4];
            float4 xv = *(const float4*)&xg[(long)(t * 16 + ty) * 2048 + n0 + tx * 4];
            float ig = a0 + rr.x + xv.x;
            float fg = a1 + rr.y + xv.y;
            float gg = a2 + rr.z + xv.z;
            float og = a3 + rr.w + xv.w;
            float keep = 1.f - done[t * 16 + ty];
            float cold = creg * keep;
            float si = 1.f / (1.f + expf(-ig));
            float sf = 1.f / (1.f + expf(-fg));
            float so = 1.f / (1.f + expf(-og));
            float cn = sf * cold + si * tanhf(gg);
            float hn = so * tanhf(cn);
            creg = cn;
            hout[ty * 512 + u] = hn;
            hs[(long)(t * 16 + ty) * 512 + u] = __float2half_rn(hn);
        }
        __threadfence();
        __syncthreads();
        if (tid == 0) {
            atomicAdd(bar, 1);
            int target = 64 * (t + 1);
            while (atomicAdd(bar, 0) < target) __nanosleep(64);
        }
        __syncthreads();
        __threadfence();
    }
    if (ks == 0) cbuf[ty * 512 + u] = creg;
}

// ---------------------------------------------------------------------------
extern "C" void kernel_launch(void* const* d_in, const int* in_sizes, int n_in,
                              void* d_out, int out_size) {
    (void)in_sizes; (void)n_in; (void)out_size;
    __half* hh = nullptr;
    float* fa = nullptr;
    cudaGetSymbolAddress((void**)&hh, g_hh);
    cudaGetSymbolAddress((void**)&fa, g_f);

    const float* x    = (const float*)d_in[0];
    const float* done = (const float*)d_in[1];
    const float* h0   = (const float*)d_in[2];
    const float* c0   = (const float*)d_in[3];
    const float* w11  = (const float*)d_in[4];
    const float* b11  = (const float*)d_in[5];
    const float* w12  = (const float*)d_in[6];
    const float* b12  = (const float*)d_in[7];
    const float* w21  = (const float*)d_in[8];
    const float* b21  = (const float*)d_in[9];
    const float* w22  = (const float*)d_in[10];
    const float* b22  = (const float*)d_in[11];
    const float* w31  = (const float*)d_in[12];
    const float* b31  = (const float*)d_in[13];
    const float* w32  = (const float*)d_in[14];
    const float* b32  = (const float*)d_in[15];
    const float* W_ih = (const float*)d_in[16];
    const float* W_hh = (const float*)d_in[17];
    const float* b_ih = (const float*)d_in[18];
    const float* b_hh = (const float*)d_in[19];
    const float* Wf   = (const float*)d_in[20];
    const float* bf   = (const float*)d_in[21];
    float* out = (float*)d_out;

    cudaFuncSetAttribute(ihw_prep_t, cudaFuncAttributeMaxDynamicSharedMemorySize, 69632);
    cudaFuncSetAttribute(lstm_all, cudaFuncAttributeMaxDynamicSharedMemorySize, 110592);

    // ---- prep (single range-dispatched launch + ihw transpose) ----
    prep_all<<<21708, 256>>>(x, hh + O_X, w11, w12, w21, w22, w31, w32,
                             hh + O_W1, hh + O_W2, hh + O_W3,
                             hh + O_W4, hh + O_W5, hh + O_W6,
                             Wf, hh + O_WFH, hh + O_WFL, W_hh, fa + F_WTHH,
                             b_ih, b_hh, fa + F_BG);
    ihw_prep_t<<<dim3(16, 16), 256, 69632>>>(W_ih, hh + O_WIHH, hh + O_WIHL);
    cudaMemcpyAsync(fa + F_H0, h0, 8192 * sizeof(float), cudaMemcpyDeviceToDevice, 0);
    cudaMemcpyAsync(fa + F_C,  c0, 8192 * sizeof(float), cudaMemcpyDeviceToDevice, 0);
    cudaMemsetAsync(fa + F_BAR, 0, sizeof(int), 0);

    // ---- conv stack ----
    conv_wm8<4, 32, 7, 32, 32, 1, 1><<<24576, 256>>>(hh + O_X, hh + O_W1, b11, hh + O_A1, nullptr);
    conv_wm8<32, 32, 6, 32, 32, 2, 1><<<5120, 256>>>(hh + O_A1, hh + O_W2, b12, hh + O_A2, nullptr);
    conv_wm8<32, 64, 5, 16, 16, 1, 1><<<4096, 256>>>(hh + O_A2, hh + O_W3, b21, hh + O_A3, nullptr);
    conv_wm8<64, 64, 4, 16, 16, 2, 1><<<768, 256>>>(hh + O_A3, hh + O_W4, b22, hh + O_A4, nullptr);
    conv_wm8<64, 128, 3, 8, 8, 1, 1><<<1024, 256>>>(hh + O_A4, hh + O_W5, b31, hh + O_A5, nullptr);
    conv_wm8<128, 128, 2, 8, 8, 2, 4><<<dim3(128, 4), 256>>>(hh + O_A5, hh + O_W6, b32, nullptr, fa + F_SCR);
    l6_red<<<1024, 256>>>(fa + F_SCR, b32, hh + O_F);

    // ---- LSTM input GEMM (BK=32) ----
    mm_wm5<2048, 2048, false><<<dim3(8, 16), 256>>>(
        hh + O_F, hh + O_WIHH, hh + O_WIHL, fa + F_BG, fa + F_XG);

    // ---- persistent LSTM ----
    lstm_all<<<64, 256, 110592>>>(fa + F_XG, fa + F_WTHH, done,
                                  fa + F_H0, fa + F_H1, fa + F_C,
                                  hh + O_HS, (int*)(fa + F_BAR));

    // ---- final FC + relu into d_out (BK=32) ----
    mm_wm5<512, 512, true><<<dim3(8, 4), 256>>>(
        hh + O_HS, hh + O_WFH, hh + O_WFL, bf, out);

    // ---- hT, cT ----
    cudaMemcpyAsync(out + 262144, fa + F_H0, 8192 * sizeof(float),
                    cudaMemcpyDeviceToDevice, 0);
    cudaMemcpyAsync(out + 270336, fa + F_C, 8192 * sizeof(float),
                    cudaMemcpyDeviceToDevice, 0);
}